// round 8
// baseline (speedup 1.0000x reference)
#include <cuda_runtime.h>
#include <math.h>

#define B_TOT 512
#define N_TOK 343
#define DIM   96
#define HEADS 3
#define HD    32
#define NW    64
#define CB_STRIDE 344
#define CB_SLICE  (N_TOK * CB_STRIDE)   // 117992

// ---------------- scratch (device globals: no allocation allowed) ----------
__device__ float g_q [(size_t)B_TOT * HEADS * N_TOK * HD];   // [B][H][N][hd], pre-scaled
__device__ float g_k [(size_t)B_TOT * HEADS * N_TOK * HD];
__device__ float g_v [(size_t)B_TOT * HEADS * N_TOK * HD];
__device__ float g_ao[(size_t)B_TOT * N_TOK * DIM];          // [B][N][H*hd]
__device__ float g_cb[(size_t)NW * HEADS * CB_SLICE + 64];   // mask+bias, stride-344 rows

// ---------------- helpers --------------------------------------------------
__device__ __forceinline__ float fast_exp(float x) {
    float y = x * 1.4426950408889634f;        // log2(e)
    y = fmaxf(y, -87.0f);
    float t = y + 12582912.0f;                // round-to-nearest magic (1.5*2^23)
    float f = y - (t - 12582912.0f);          // f in [-0.5, 0.5]
    float p = 1.3333558146428443e-3f;
    p = fmaf(p, f, 9.618129107628477e-3f);
    p = fmaf(p, f, 5.550410866482158e-2f);
    p = fmaf(p, f, 2.402265069591007e-1f);
    p = fmaf(p, f, 6.931471805599453e-1f);
    p = fmaf(p, f, 1.0f);
    return __int_as_float(__float_as_int(p) + (__float_as_int(t) << 23));
}

__device__ __forceinline__ unsigned f2tf(float x) {
    unsigned r;
    asm("cvt.rna.tf32.f32 %0, %1;" : "=r"(r) : "f"(x));
    return r;
}

__device__ __forceinline__ void mma_tf32(float& c0, float& c1, float& c2, float& c3,
                                         unsigned a0, unsigned a1, unsigned a2, unsigned a3,
                                         unsigned b0, unsigned b1) {
    asm volatile("mma.sync.aligned.m16n8k8.row.col.f32.tf32.tf32.f32 "
                 "{%0,%1,%2,%3}, {%4,%5,%6,%7}, {%8,%9}, {%0,%1,%2,%3};"
                 : "+f"(c0), "+f"(c1), "+f"(c2), "+f"(c3)
                 : "r"(a0), "r"(a1), "r"(a2), "r"(a3), "r"(b0), "r"(b1));
}

// ---------------- kernel 0: combined bias table (stride 344) ---------------
__global__ __launch_bounds__(352)
void cb_kernel(const float* __restrict__ mask,
               const float* __restrict__ rpb,
               const int*   __restrict__ relidx) {
    const int i  = blockIdx.x;
    const int wh = blockIdx.y;
    const int w  = wh / HEADS;
    const int h  = wh - w * HEADS;
    const int j  = threadIdx.x;
    if (j < N_TOK) {
        int rel = relidx[i * N_TOK + j];
        g_cb[(size_t)wh * CB_SLICE + i * CB_STRIDE + j] =
            mask[(size_t)w * N_TOK * N_TOK + i * N_TOK + j] + rpb[rel * HEADS + h];
    }
}

// ---------------- kernel 1: QKV GEMM, 64-row CTA, 3 CTAs/SM ---------------
// 8 warps: warp = (col-group cg: 24 cols) x (row-half mh: 32 rows), streams
// 2 m16-stripes. xs pre-converted to tf32 bits. Low-reg: B-frags via LDS.
__global__ __launch_bounds__(256, 3)
void qkv_kernel(const float* __restrict__ x,
                const float* __restrict__ w,
                const float* __restrict__ bias) {
    extern __shared__ float smf[];
    unsigned* xs    = (unsigned*)smf;            // [64][100] tf32 bits : 25600B
    unsigned* wfrag = (unsigned*)smf + 6400;     // [144][64]          : 36864B
    float*    bs    = smf + 6400 + 9216;         // [96]
    const int tid = threadIdx.x;
    const int m0  = blockIdx.x * 64;

    for (int idx = tid; idx < 64 * 96; idx += 256) {
        int r = idx / 96, c = idx - r * 96;
        xs[r * 100 + c] = f2tf(x[(size_t)m0 * 96 + idx]);
    }

    const int wp   = tid >> 5;
    const int lane = tid & 31;
    const int g    = lane >> 2;
    const int tig  = lane & 3;
    const int cg   = wp & 3;        // col group: nt = 3*cg + ntl
    const int mh   = wp >> 2;       // row half: rows [32*mh, 32*mh+32)
    const float qscale = 0.17677669529663687f;

    for (int third = 0; third < 3; third++) {
        __syncthreads();
        for (int idx = tid; idx < 12 * 12 * 32; idx += 256) {
            int t = idx >> 5, l = idx & 31;
            int nt = t / 12, kk = t - nt * 12;
            int gl = l >> 2, tl = l & 3;
            int c  = third * 96 + nt * 8 + gl;
            int k0 = kk * 8 + tl;
            wfrag[t * 64 + l * 2]     = f2tf(w[c * 96 + k0]);
            wfrag[t * 64 + l * 2 + 1] = f2tf(w[c * 96 + k0 + 4]);
        }
        if (tid < 96) bs[tid] = bias[third * 96 + tid];
        __syncthreads();

        #pragma unroll
        for (int s = 0; s < 2; s++) {
            const unsigned* xrA = xs + (mh * 32 + s * 16 + g) * 100;
            const unsigned* xrB = xrA + 800;

            float acc[3][4];
            #pragma unroll
            for (int ntl = 0; ntl < 3; ntl++)
                #pragma unroll
                for (int e = 0; e < 4; e++) acc[ntl][e] = 0.f;

            #pragma unroll
            for (int kk = 0; kk < 12; kk++) {
                unsigned a0 = xrA[kk * 8 + tig];
                unsigned a1 = xrB[kk * 8 + tig];
                unsigned a2 = xrA[kk * 8 + tig + 4];
                unsigned a3 = xrB[kk * 8 + tig + 4];
                #pragma unroll
                for (int ntl = 0; ntl < 3; ntl++) {
                    uint2 bb = *(const uint2*)(wfrag + ((3 * cg + ntl) * 12 + kk) * 64 + lane * 2);
                    mma_tf32(acc[ntl][0], acc[ntl][1], acc[ntl][2], acc[ntl][3],
                             a0, a1, a2, a3, bb.x, bb.y);
                }
            }

            const int mA = m0 + mh * 32 + s * 16 + g;
            const int mB = mA + 8;
            const int bA = mA / N_TOK, nA = mA - bA * N_TOK;
            const int bB = mB / N_TOK, nB = mB - bB * N_TOK;
            #pragma unroll
            for (int ntl = 0; ntl < 3; ntl++) {
                int c0 = (3 * cg + ntl) * 8 + 2 * tig;
                int hh = c0 >> 5, d = c0 & 31;
                float bb0 = bs[c0], bb1 = bs[c0 + 1];
                float2 vA = make_float2(acc[ntl][0] + bb0, acc[ntl][1] + bb1);
                float2 vB = make_float2(acc[ntl][2] + bb0, acc[ntl][3] + bb1);
                size_t offA = (((size_t)(bA * HEADS + hh)) * N_TOK + nA) * HD + d;
                size_t offB = (((size_t)(bB * HEADS + hh)) * N_TOK + nB) * HD + d;
                if (third == 0) {
                    vA.x *= qscale; vA.y *= qscale; vB.x *= qscale; vB.y *= qscale;
                    *(float2*)(g_q + offA) = vA; *(float2*)(g_q + offB) = vB;
                } else if (third == 1) {
                    *(float2*)(g_k + offA) = vA; *(float2*)(g_k + offB) = vB;
                } else {
                    *(float2*)(g_v + offA) = vA; *(float2*)(g_v + offB) = vB;
                }
            }
        }
    }
}

// ---------------- kernel 2: fused attention, 2 CTAs/SM ---------------------
// 352 threads = 11 warps, each warp does 2 m16 query stripes sequentially
// (22 stripes = 352 rows >= 343). 2 CTAs co-resident per SM: one CTA's
// LDG-bound frag build overlaps the other's mma mainloop.
__global__ __launch_bounds__(352, 2)
void attn_kernel() {
    extern __shared__ unsigned smu[];
    unsigned* kfrag = smu;               // [44*4][64] : 11264
    unsigned* vfrag = smu + 11264;       // [44*4][64] : 11264

    const int bid  = blockIdx.x;
    const int wh   = bid >> 3;                 // window*3 + h
    const int rep  = bid & 7;
    const int win  = wh / HEADS;
    const int h    = wh - win * HEADS;
    const int b    = rep * NW + win;
    const int tid  = threadIdx.x;
    const int lane = tid & 31;
    const int w    = tid >> 5;           // 0..10
    const int g    = lane >> 2;          // 0..7
    const int tig  = lane & 3;           // 0..3

    const size_t bh_off = ((size_t)(b * HEADS + h)) * N_TOK * HD;
    const float* kg = g_k + bh_off;
    const float* vg = g_v + bh_off;
    const float* qg = g_q + bh_off;
    const float* cbp = g_cb + (size_t)wh * CB_SLICE;

    // ---- build K B-fragments (44 tiles, padded rows zero) ----
    for (int idx = tid; idx < 44 * 4 * 32; idx += 352) {
        int tile = idx >> 5, l = idx & 31;
        int nt = tile >> 2, kk = tile & 3;
        int gl = l >> 2, tl = l & 3;
        int n = nt * 8 + gl;
        int d0 = kk * 8 + tl;
        float v0 = (n < N_TOK) ? kg[n * 32 + d0]     : 0.f;
        float v1 = (n < N_TOK) ? kg[n * 32 + d0 + 4] : 0.f;
        kfrag[tile * 64 + l * 2]     = f2tf(v0);
        kfrag[tile * 64 + l * 2 + 1] = f2tf(v1);
    }
    // ---- build V B-fragments ----
    for (int idx = tid; idx < 44 * 4 * 32; idx += 352) {
        int tile = idx >> 5, l = idx & 31;
        int kt = tile >> 2, nn = tile & 3;
        int gl = l >> 2, tl = l & 3;
        int k0 = kt * 8;
        float v0 = (k0 + tl     < N_TOK) ? vg[(k0 + tl)     * 32 + nn * 8 + gl] : 0.f;
        float v1 = (k0 + tl + 4 < N_TOK) ? vg[(k0 + tl + 4) * 32 + nn * 8 + gl] : 0.f;
        vfrag[tile * 64 + l * 2]     = f2tf(v0);
        vfrag[tile * 64 + l * 2 + 1] = f2tf(v1);
    }
    __syncthreads();

    const int srcq0 = (lane & ~3) | (tig >> 1);
    const int srcq1 = srcq0 + 2;
    const bool oddt = tig & 1;

    #pragma unroll 1
    for (int sp = 0; sp < 2; sp++) {
        const int i0 = (w * 2 + sp) * 16;
        const int iA = i0 + g, iB = i0 + g + 8;
        const bool vA = (iA < N_TOK), vB = (iB < N_TOK);

        unsigned qa[4][4];
        #pragma unroll
        for (int kk = 0; kk < 4; kk++) {
            int d0 = kk * 8 + tig;
            qa[kk][0] = vA ? f2tf(qg[iA * 32 + d0])     : 0u;
            qa[kk][1] = vB ? f2tf(qg[iB * 32 + d0])     : 0u;
            qa[kk][2] = vA ? f2tf(qg[iA * 32 + d0 + 4]) : 0u;
            qa[kk][3] = vB ? f2tf(qg[iB * 32 + d0 + 4]) : 0u;
        }

        float av[4][4];
        #pragma unroll
        for (int nn = 0; nn < 4; nn++)
            #pragma unroll
            for (int e = 0; e < 4; e++) av[nn][e] = 0.f;

        float sumA = 0.f, sumB = 0.f;
        const float* cbA = cbp + (size_t)iA * CB_STRIDE;
        const float* cbB = cbp + (size_t)iB * CB_STRIDE;

        for (int tp = 0; tp < 22; tp++) {
            // ---- stage 1: bias loads for both tiles ----
            float cb[2][4];
            #pragma unroll
            for (int tt = 0; tt < 2; tt++) {
                const int j0 = (2 * tp + tt) * 8 + 2 * tig;
                float c00, c01, c10, c11;
                if (vA && j0 < N_TOK) {
                    float2 t = *(const float2*)(cbA + j0);
                    c00 = t.x; c01 = t.y;
                } else { c00 = c01 = -1e30f; }
                if (vB && j0 < N_TOK) {
                    float2 t = *(const float2*)(cbB + j0);
                    c10 = t.x; c11 = t.y;
                } else { c10 = c11 = -1e30f; }
                if (j0 + 1 >= N_TOK) { c01 = -1e30f; c11 = -1e30f; }
                cb[tt][0] = c00; cb[tt][1] = c01; cb[tt][2] = c10; cb[tt][3] = c11;
            }

            // ---- stage 2: QK mma, two independent chains ----
            float c[2][4];
            #pragma unroll
            for (int tt = 0; tt < 2; tt++) {
                c[tt][0] = c[tt][1] = c[tt][2] = c[tt][3] = 0.f;
                const int ntg = 2 * tp + tt;
                #pragma unroll
                for (int kk = 0; kk < 4; kk++) {
                    uint2 bb = *(const uint2*)(kfrag + (ntg * 4 + kk) * 64 + lane * 2);
                    mma_tf32(c[tt][0], c[tt][1], c[tt][2], c[tt][3],
                             qa[kk][0], qa[kk][1], qa[kk][2], qa[kk][3], bb.x, bb.y);
                }
            }

            // ---- stage 3: exp ----
            float p[2][4];
            #pragma unroll
            for (int tt = 0; tt < 2; tt++) {
                p[tt][0] = fast_exp(c[tt][0] + cb[tt][0]);
                p[tt][1] = fast_exp(c[tt][1] + cb[tt][1]);
                p[tt][2] = fast_exp(c[tt][2] + cb[tt][2]);
                p[tt][3] = fast_exp(c[tt][3] + cb[tt][3]);
                sumA += p[tt][0] + p[tt][1];
                sumB += p[tt][2] + p[tt][3];
            }

            // ---- stage 4: reshape C-frag -> A-frag ----
            unsigned af[2][4];
            #pragma unroll
            for (int tt = 0; tt < 2; tt++) {
                unsigned t0 = f2tf(p[tt][0]), t1 = f2tf(p[tt][1]);
                unsigned t2 = f2tf(p[tt][2]), t3 = f2tf(p[tt][3]);
                unsigned u0 = __shfl_sync(0xffffffffu, t0, srcq0);
                unsigned u1 = __shfl_sync(0xffffffffu, t1, srcq0);
                unsigned u2 = __shfl_sync(0xffffffffu, t2, srcq0);
                unsigned u3 = __shfl_sync(0xffffffffu, t3, srcq0);
                unsigned w0 = __shfl_sync(0xffffffffu, t0, srcq1);
                unsigned w1 = __shfl_sync(0xffffffffu, t1, srcq1);
                unsigned w2 = __shfl_sync(0xffffffffu, t2, srcq1);
                unsigned w3 = __shfl_sync(0xffffffffu, t3, srcq1);
                af[tt][0] = oddt ? u1 : u0;
                af[tt][1] = oddt ? u3 : u2;
                af[tt][2] = oddt ? w1 : w0;
                af[tt][3] = oddt ? w3 : w2;
            }

            // ---- stage 5: AV mma ----
            #pragma unroll
            for (int tt = 0; tt < 2; tt++) {
                const int ntg = 2 * tp + tt;
                #pragma unroll
                for (int nn = 0; nn < 4; nn++) {
                    uint2 bb = *(const uint2*)(vfrag + (ntg * 4 + nn) * 64 + lane * 2);
                    mma_tf32(av[nn][0], av[nn][1], av[nn][2], av[nn][3],
                             af[tt][0], af[tt][1], af[tt][2], af[tt][3], bb.x, bb.y);
                }
            }
        }

        sumA += __shfl_xor_sync(0xffffffffu, sumA, 1);
        sumA += __shfl_xor_sync(0xffffffffu, sumA, 2);
        sumB += __shfl_xor_sync(0xffffffffu, sumB, 1);
        sumB += __shfl_xor_sync(0xffffffffu, sumB, 2);
        const float invA = 1.0f / sumA;
        const float invB = 1.0f / sumB;

        #pragma unroll
        for (int nn = 0; nn < 4; nn++) {
            const int d = nn * 8 + 2 * tig;
            if (vA) {
                float2 o = make_float2(av[nn][0] * invA, av[nn][1] * invA);
                *(float2*)(g_ao + ((size_t)b * N_TOK + iA) * DIM + h * HD + d) = o;
            }
            if (vB) {
                float2 o = make_float2(av[nn][2] * invB, av[nn][3] * invB);
                *(float2*)(g_ao + ((size_t)b * N_TOK + iB) * DIM + h * HD + d) = o;
            }
        }
    }
}

// ---------------- kernel 3: output projection, 64-row CTA, 3 CTAs/SM -------
__global__ __launch_bounds__(256, 3)
void proj_kernel(const float* __restrict__ w,
                 const float* __restrict__ bias,
                 float* __restrict__ out) {
    extern __shared__ float smf[];
    unsigned* xs    = (unsigned*)smf;            // [64][100] tf32 bits
    unsigned* wfrag = (unsigned*)smf + 6400;     // [144][64]
    float*    bs    = smf + 6400 + 9216;         // [96]
    const int tid = threadIdx.x;
    const int m0  = blockIdx.x * 64;

    for (int idx = tid; idx < 12 * 12 * 32; idx += 256) {
        int t = idx >> 5, l = idx & 31;
        int nt = t / 12, kk = t - nt * 12;
        int gl = l >> 2, tl = l & 3;
        int c  = nt * 8 + gl;
        int k0 = kk * 8 + tl;
        wfrag[t * 64 + l * 2]     = f2tf(w[c * 96 + k0]);
        wfrag[t * 64 + l * 2 + 1] = f2tf(w[c * 96 + k0 + 4]);
    }
    if (tid < 96) bs[tid] = bias[tid];
    for (int idx = tid; idx < 64 * 96; idx += 256) {
        int r = idx / 96, c = idx - r * 96;
        xs[r * 100 + c] = f2tf(g_ao[(size_t)m0 * 96 + idx]);
    }
    __syncthreads();

    const int wp   = tid >> 5;
    const int lane = tid & 31;
    const int g    = lane >> 2;
    const int tig  = lane & 3;
    const int cg   = wp & 3;
    const int mh   = wp >> 2;

    #pragma unroll
    for (int s = 0; s < 2; s++) {
        const unsigned* xrA = xs + (mh * 32 + s * 16 + g) * 100;
        const unsigned* xrB = xrA + 800;

        float acc[3][4];
        #pragma unroll
        for (int ntl = 0; ntl < 3; ntl++)
            #pragma unroll
            for (int e = 0; e < 4; e++) acc[ntl][e] = 0.f;

        #pragma unroll
        for (int kk = 0; kk < 12; kk++) {
            unsigned a0 = xrA[kk * 8 + tig];
            unsigned a1 = xrB[kk * 8 + tig];
            unsigned a2 = xrA[kk * 8 + tig + 4];
            unsigned a3 = xrB[kk * 8 + tig + 4];
            #pragma unroll
            for (int ntl = 0; ntl < 3; ntl++) {
                uint2 bb = *(const uint2*)(wfrag + ((3 * cg + ntl) * 12 + kk) * 64 + lane * 2);
                mma_tf32(acc[ntl][0], acc[ntl][1], acc[ntl][2], acc[ntl][3],
                         a0, a1, a2, a3, bb.x, bb.y);
            }
        }

        const size_t mA = m0 + mh * 32 + s * 16 + g;
        const size_t mB = mA + 8;
        #pragma unroll
        for (int ntl = 0; ntl < 3; ntl++) {
            int c0 = (3 * cg + ntl) * 8 + 2 * tig;
            float bb0 = bs[c0], bb1 = bs[c0 + 1];
            *(float2*)(out + mA * 96 + c0) = make_float2(acc[ntl][0] + bb0, acc[ntl][1] + bb1);
            *(float2*)(out + mB * 96 + c0) = make_float2(acc[ntl][2] + bb0, acc[ntl][3] + bb1);
        }
    }
}

// ---------------- launch ---------------------------------------------------
extern "C" void kernel_launch(void* const* d_in, const int* in_sizes, int n_in,
                              void* d_out, int out_size) {
    const float* x      = (const float*)d_in[0];
    const float* mask   = (const float*)d_in[1];
    const float* qkv_w  = (const float*)d_in[2];
    const float* qkv_b  = (const float*)d_in[3];
    const float* proj_w = (const float*)d_in[4];
    const float* proj_b = (const float*)d_in[5];
    const float* rpb    = (const float*)d_in[6];
    const int*   relidx = (const int*)d_in[7];
    float* out = (float*)d_out;

    const int smem_attn = (11264 + 11264) * 4;       //  90,112 B
    const int smem_gemm = (6400 + 9216 + 96) * 4;    //  62,848 B
    cudaFuncSetAttribute(attn_kernel, cudaFuncAttributeMaxDynamicSharedMemorySize, smem_attn);
    cudaFuncSetAttribute(qkv_kernel,  cudaFuncAttributeMaxDynamicSharedMemorySize, smem_gemm);
    cudaFuncSetAttribute(proj_kernel, cudaFuncAttributeMaxDynamicSharedMemorySize, smem_gemm);

    cb_kernel  <<<dim3(N_TOK, NW * HEADS), 352>>>(mask, rpb, relidx);
    qkv_kernel <<<2744, 256, smem_gemm>>>(x, qkv_w, qkv_b);
    attn_kernel<<<B_TOT * HEADS, 352, smem_attn>>>();
    proj_kernel<<<2744, 256, smem_gemm>>>(proj_w, proj_b, out);
    (void)in_sizes; (void)n_in; (void)out_size;
}

// round 9
// speedup vs baseline: 1.0600x; 1.0600x over previous
#include <cuda_runtime.h>
#include <math.h>

#define B_TOT 512
#define N_TOK 343
#define DIM   96
#define HEADS 3
#define HD    32
#define NW    64
#define CB_STRIDE 344
#define CB_SLICE  (N_TOK * CB_STRIDE)   // 117992

// ---------------- scratch (device globals: no allocation allowed) ----------
__device__ float g_ao[(size_t)B_TOT * N_TOK * DIM];          // [B][N][H*hd]
__device__ float g_cb[(size_t)NW * HEADS * CB_SLICE + 64];   // mask+bias, stride-344 rows

// ---------------- helpers --------------------------------------------------
__device__ __forceinline__ float fast_exp(float x) {
    float y = x * 1.4426950408889634f;        // log2(e)
    y = fmaxf(y, -87.0f);
    float t = y + 12582912.0f;                // round-to-nearest magic (1.5*2^23)
    float f = y - (t - 12582912.0f);          // f in [-0.5, 0.5]
    float p = 1.3333558146428443e-3f;
    p = fmaf(p, f, 9.618129107628477e-3f);
    p = fmaf(p, f, 5.550410866482158e-2f);
    p = fmaf(p, f, 2.402265069591007e-1f);
    p = fmaf(p, f, 6.931471805599453e-1f);
    p = fmaf(p, f, 1.0f);
    return __int_as_float(__float_as_int(p) + (__float_as_int(t) << 23));
}

__device__ __forceinline__ unsigned f2tf(float x) {
    unsigned r;
    asm("cvt.rna.tf32.f32 %0, %1;" : "=r"(r) : "f"(x));
    return r;
}

__device__ __forceinline__ void mma_tf32(float& c0, float& c1, float& c2, float& c3,
                                         unsigned a0, unsigned a1, unsigned a2, unsigned a3,
                                         unsigned b0, unsigned b1) {
    asm volatile("mma.sync.aligned.m16n8k8.row.col.f32.tf32.tf32.f32 "
                 "{%0,%1,%2,%3}, {%4,%5,%6,%7}, {%8,%9}, {%0,%1,%2,%3};"
                 : "+f"(c0), "+f"(c1), "+f"(c2), "+f"(c3)
                 : "r"(a0), "r"(a1), "r"(a2), "r"(a3), "r"(b0), "r"(b1));
}

// kfrag word index for K value at (row n, col d)
__device__ __forceinline__ int kpos(int n, int d) {
    return (((n >> 3) * 4 + (d >> 3)) << 6) + (((n & 7) << 2) | (d & 3)) * 2 + ((d & 7) >> 2);
}
// vfrag word index for V value at (row j, col d)
__device__ __forceinline__ int vpos(int j, int d) {
    return (((j >> 3) * 4 + (d >> 3)) << 6) + (((d & 7) << 2) | (j & 3)) * 2 + ((j & 7) >> 2);
}

// ---------------- kernel 0: combined bias table (stride 344) ---------------
__global__ __launch_bounds__(352)
void cb_kernel(const float* __restrict__ mask,
               const float* __restrict__ rpb,
               const int*   __restrict__ relidx) {
    const int i  = blockIdx.x;
    const int wh = blockIdx.y;
    const int w  = wh / HEADS;
    const int h  = wh - w * HEADS;
    const int j  = threadIdx.x;
    if (j < N_TOK) {
        int rel = relidx[i * N_TOK + j];
        g_cb[(size_t)wh * CB_SLICE + i * CB_STRIDE + j] =
            mask[(size_t)w * N_TOK * N_TOK + i * N_TOK + j] + rpb[rel * HEADS + h];
    }
}

// ---------------- kernel 1: FUSED qkv + attention --------------------------
// One CTA = (window, head). Prologue computes K,V directly into B-fragment
// smem layouts and per-warp Q A-fragments (shfl reshape) from x and the
// head's weight slices. Mainloop: paired-tile QK->exp->reshape->AV with
// cb double-buffering. Rows >= N_TOK are killed by cb poison (p = 0).
__global__ __launch_bounds__(704, 1)
void attn_kernel(const float* __restrict__ xg,
                 const float* __restrict__ qkvw,
                 const float* __restrict__ qkvb) {
    extern __shared__ unsigned smu[];
    unsigned* kfrag = smu;               // [44*4][64] : 11264
    unsigned* vfrag = smu + 11264;       // [44*4][64] : 11264
    unsigned* wf    = smu + 22528;       // [3][4][12][64] : 9216
    unsigned* xs    = smu + 31744;       // [128][100] tf32 bits : 12800
    float*    bsm   = (float*)(smu + 44544);   // [288]

    const int bid  = blockIdx.x;
    const int wh   = bid >> 3;                 // window*3 + h
    const int rep  = bid & 7;
    const int win  = wh / HEADS;
    const int h    = wh - win * HEADS;
    const int b    = rep * NW + win;
    const int tid  = threadIdx.x;
    const int lane = tid & 31;
    const int w    = tid >> 5;           // 0..21
    const int g    = lane >> 2;          // 0..7
    const int tig  = lane & 3;           // 0..3

    const float* xrow0 = xg + (size_t)b * N_TOK * DIM;
    const float* cbp   = g_cb + (size_t)wh * CB_SLICE;
    const float qscale = 0.17677669529663687f;

    // ---- stage weight B-fragments for this head: thirds q,k,v x 32 cols ----
    // wf[(third*48 + nt*12 + kk)*64 + l*2 + e] = W[third*96 + h*32 + nt*8 + gl][kk*8 + tl + 4e]
    for (int idx = tid; idx < 3 * 4 * 12 * 32; idx += 704) {
        int t = idx >> 5, l = idx & 31;
        int third = t / 48, rem = t - third * 48;
        int nt = rem / 12, kk = rem - nt * 12;
        int gl = l >> 2, tl = l & 3;
        int c  = third * 96 + h * 32 + nt * 8 + gl;
        int k0 = kk * 8 + tl;
        wf[t * 64 + l * 2]     = f2tf(qkvw[c * 96 + k0]);
        wf[t * 64 + l * 2 + 1] = f2tf(qkvw[c * 96 + k0 + 4]);
    }
    for (int idx = tid; idx < 96; idx += 704) {
        bsm[idx]       = qkvb[idx + h * 32 + ((idx >> 5) * 64)];  // third=idx>>5, col=idx&31
    }
    // simpler exact bias staging: bsm[third*32 + cc] = qkvb[third*96 + h*32 + cc]
    // (the expression above implements exactly this: idx = third*32+cc ->
    //  qkvb[third*32+cc + h*32 + third*64] = qkvb[third*96 + h*32 + cc])

    unsigned qa[4][4];   // Q A-fragments, filled during the owning chunk

    // ---- chunks of 128 rows: compute K,V into frags; Q for owning warps ----
    #pragma unroll 1
    for (int c = 0; c < 3; c++) {
        if (c > 0) __syncthreads();
        for (int idx = tid; idx < 128 * 96; idx += 704) {
            int r = idx / 96, cc = idx - r * 96;
            int n = 128 * c + r;
            float v = (n < N_TOK) ? xrow0[(size_t)n * 96 + cc] : 0.f;
            xs[r * 100 + cc] = f2tf(v);
        }
        __syncthreads();

        // K/V units: u = (s<<2) | (third01<<1) | nhalf, 32 units over 22 warps
        for (int u = w; u < 32; u += 22) {
            int s = u >> 2, th = (u >> 1) & 1, nh = u & 1;
            const unsigned* xrA = xs + (s * 16 + g) * 100;
            const unsigned* xrB = xrA + 800;
            #pragma unroll
            for (int ntl = 0; ntl < 2; ntl++) {
                int nt = nh * 2 + ntl;
                float a0f = 0.f, a1f = 0.f, a2f = 0.f, a3f = 0.f;
                #pragma unroll
                for (int kk = 0; kk < 12; kk++) {
                    unsigned a0 = xrA[kk * 8 + tig];
                    unsigned a1 = xrB[kk * 8 + tig];
                    unsigned a2 = xrA[kk * 8 + tig + 4];
                    unsigned a3 = xrB[kk * 8 + tig + 4];
                    uint2 bb = *(const uint2*)(wf + (((th + 1) * 48) + nt * 12 + kk) * 64 + lane * 2);
                    mma_tf32(a0f, a1f, a2f, a3f, a0, a1, a2, a3, bb.x, bb.y);
                }
                int c0 = nt * 8 + 2 * tig;
                float b0 = bsm[(th + 1) * 32 + c0];
                float b1 = bsm[(th + 1) * 32 + c0 + 1];
                int nA = 128 * c + s * 16 + g;
                int nB = nA + 8;
                float v00 = a0f + b0, v01 = a1f + b1;    // row nA
                float v10 = a2f + b0, v11 = a3f + b1;    // row nB
                if (th == 0) {
                    if (nA < 352) {
                        kfrag[kpos(nA, c0)]     = f2tf(v00);
                        kfrag[kpos(nA, c0 + 1)] = f2tf(v01);
                    }
                    if (nB < 352) {
                        kfrag[kpos(nB, c0)]     = f2tf(v10);
                        kfrag[kpos(nB, c0 + 1)] = f2tf(v11);
                    }
                } else {
                    if (nA < 352) {
                        vfrag[vpos(nA, c0)]     = f2tf(v00);
                        vfrag[vpos(nA, c0 + 1)] = f2tf(v01);
                    }
                    if (nB < 352) {
                        vfrag[vpos(nB, c0)]     = f2tf(v10);
                        vfrag[vpos(nB, c0 + 1)] = f2tf(v11);
                    }
                }
            }
        }

        // Q for warps whose stripe lives in this chunk (stripe w: rows 16w..16w+15)
        if ((w >> 3) == c) {
            const int s = w & 7;
            const int srcq0 = (lane & ~3) | (tig >> 1);
            const int srcq1 = srcq0 + 2;
            const bool oddt = tig & 1;
            const unsigned* xrA = xs + (s * 16 + g) * 100;
            const unsigned* xrB = xrA + 800;
            #pragma unroll
            for (int nt = 0; nt < 4; nt++) {
                float a0f = 0.f, a1f = 0.f, a2f = 0.f, a3f = 0.f;
                #pragma unroll
                for (int kk = 0; kk < 12; kk++) {
                    unsigned a0 = xrA[kk * 8 + tig];
                    unsigned a1 = xrB[kk * 8 + tig];
                    unsigned a2 = xrA[kk * 8 + tig + 4];
                    unsigned a3 = xrB[kk * 8 + tig + 4];
                    uint2 bb = *(const uint2*)(wf + (nt * 12 + kk) * 64 + lane * 2);
                    mma_tf32(a0f, a1f, a2f, a3f, a0, a1, a2, a3, bb.x, bb.y);
                }
                int c0 = nt * 8 + 2 * tig;
                float b0 = bsm[c0], b1 = bsm[c0 + 1];
                unsigned t0 = f2tf((a0f + b0) * qscale);   // (rowA, c0)
                unsigned t1 = f2tf((a1f + b1) * qscale);   // (rowA, c0+1)
                unsigned t2 = f2tf((a2f + b0) * qscale);   // (rowB, c0)
                unsigned t3 = f2tf((a3f + b1) * qscale);   // (rowB, c0+1)
                unsigned u0 = __shfl_sync(0xffffffffu, t0, srcq0);
                unsigned u1 = __shfl_sync(0xffffffffu, t1, srcq0);
                unsigned u2 = __shfl_sync(0xffffffffu, t2, srcq0);
                unsigned u3 = __shfl_sync(0xffffffffu, t3, srcq0);
                unsigned w0 = __shfl_sync(0xffffffffu, t0, srcq1);
                unsigned w1 = __shfl_sync(0xffffffffu, t1, srcq1);
                unsigned w2 = __shfl_sync(0xffffffffu, t2, srcq1);
                unsigned w3 = __shfl_sync(0xffffffffu, t3, srcq1);
                qa[nt][0] = oddt ? u1 : u0;   // Q[iA, 8nt+tig]
                qa[nt][1] = oddt ? u3 : u2;   // Q[iB, 8nt+tig]
                qa[nt][2] = oddt ? w1 : w0;   // Q[iA, 8nt+tig+4]
                qa[nt][3] = oddt ? w3 : w2;   // Q[iB, 8nt+tig+4]
            }
        }
    }
    __syncthreads();

    // ---- mainloop ----
    const int i0 = w * 16;
    const int iA = i0 + g, iB = i0 + g + 8;
    const bool vA = (iA < N_TOK), vB = (iB < N_TOK);
    const int srcq0 = (lane & ~3) | (tig >> 1);
    const int srcq1 = srcq0 + 2;
    const bool oddt = tig & 1;

    float av[4][4];
    #pragma unroll
    for (int nn = 0; nn < 4; nn++)
        #pragma unroll
        for (int e = 0; e < 4; e++) av[nn][e] = 0.f;

    float sumA = 0.f, sumB = 0.f;
    const float* cbA = cbp + (size_t)iA * CB_STRIDE;
    const float* cbB = cbp + (size_t)iB * CB_STRIDE;

    // cb double buffer: load pair tp into cbq before the loop
    float cbq[2][4];
    #pragma unroll
    for (int tt = 0; tt < 2; tt++) {
        const int j0 = tt * 8 + 2 * tig;
        float c00, c01, c10, c11;
        if (vA) { float2 t = *(const float2*)(cbA + j0); c00 = t.x; c01 = t.y; }
        else    { c00 = c01 = -1e30f; }
        if (vB) { float2 t = *(const float2*)(cbB + j0); c10 = t.x; c11 = t.y; }
        else    { c10 = c11 = -1e30f; }
        cbq[tt][0] = c00; cbq[tt][1] = c01; cbq[tt][2] = c10; cbq[tt][3] = c11;
    }

    #pragma unroll 1
    for (int tp = 0; tp < 22; tp++) {
        // ---- prefetch cb for next tile pair ----
        float cbn[2][4];
        if (tp < 21) {
            #pragma unroll
            for (int tt = 0; tt < 2; tt++) {
                const int j0 = (2 * (tp + 1) + tt) * 8 + 2 * tig;
                float c00, c01, c10, c11;
                if (vA && j0 < N_TOK) { float2 t = *(const float2*)(cbA + j0); c00 = t.x; c01 = t.y; }
                else                  { c00 = c01 = -1e30f; }
                if (vB && j0 < N_TOK) { float2 t = *(const float2*)(cbB + j0); c10 = t.x; c11 = t.y; }
                else                  { c10 = c11 = -1e30f; }
                if (j0 + 1 >= N_TOK)  { c01 = -1e30f; c11 = -1e30f; }
                cbn[tt][0] = c00; cbn[tt][1] = c01; cbn[tt][2] = c10; cbn[tt][3] = c11;
            }
        }

        // ---- QK mma, two independent chains ----
        float c[2][4];
        #pragma unroll
        for (int tt = 0; tt < 2; tt++) {
            c[tt][0] = c[tt][1] = c[tt][2] = c[tt][3] = 0.f;
            const int ntg = 2 * tp + tt;
            #pragma unroll
            for (int kk = 0; kk < 4; kk++) {
                uint2 bb = *(const uint2*)(kfrag + (ntg * 4 + kk) * 64 + lane * 2);
                mma_tf32(c[tt][0], c[tt][1], c[tt][2], c[tt][3],
                         qa[kk][0], qa[kk][1], qa[kk][2], qa[kk][3], bb.x, bb.y);
            }
        }

        // ---- exp ----
        float p[2][4];
        #pragma unroll
        for (int tt = 0; tt < 2; tt++) {
            p[tt][0] = fast_exp(c[tt][0] + cbq[tt][0]);
            p[tt][1] = fast_exp(c[tt][1] + cbq[tt][1]);
            p[tt][2] = fast_exp(c[tt][2] + cbq[tt][2]);
            p[tt][3] = fast_exp(c[tt][3] + cbq[tt][3]);
            sumA += p[tt][0] + p[tt][1];
            sumB += p[tt][2] + p[tt][3];
        }

        // ---- reshape C-frag -> A-frag ----
        unsigned af[2][4];
        #pragma unroll
        for (int tt = 0; tt < 2; tt++) {
            unsigned t0 = f2tf(p[tt][0]), t1 = f2tf(p[tt][1]);
            unsigned t2 = f2tf(p[tt][2]), t3 = f2tf(p[tt][3]);
            unsigned u0 = __shfl_sync(0xffffffffu, t0, srcq0);
            unsigned u1 = __shfl_sync(0xffffffffu, t1, srcq0);
            unsigned u2 = __shfl_sync(0xffffffffu, t2, srcq0);
            unsigned u3 = __shfl_sync(0xffffffffu, t3, srcq0);
            unsigned w0 = __shfl_sync(0xffffffffu, t0, srcq1);
            unsigned w1 = __shfl_sync(0xffffffffu, t1, srcq1);
            unsigned w2 = __shfl_sync(0xffffffffu, t2, srcq1);
            unsigned w3 = __shfl_sync(0xffffffffu, t3, srcq1);
            af[tt][0] = oddt ? u1 : u0;
            af[tt][1] = oddt ? u3 : u2;
            af[tt][2] = oddt ? w1 : w0;
            af[tt][3] = oddt ? w3 : w2;
        }

        // ---- AV mma ----
        #pragma unroll
        for (int tt = 0; tt < 2; tt++) {
            const int ntg = 2 * tp + tt;
            #pragma unroll
            for (int nn = 0; nn < 4; nn++) {
                uint2 bb = *(const uint2*)(vfrag + (ntg * 4 + nn) * 64 + lane * 2);
                mma_tf32(av[nn][0], av[nn][1], av[nn][2], av[nn][3],
                         af[tt][0], af[tt][1], af[tt][2], af[tt][3], bb.x, bb.y);
            }
        }

        if (tp < 21) {
            #pragma unroll
            for (int tt = 0; tt < 2; tt++)
                #pragma unroll
                for (int e = 0; e < 4; e++) cbq[tt][e] = cbn[tt][e];
        }
    }

    sumA += __shfl_xor_sync(0xffffffffu, sumA, 1);
    sumA += __shfl_xor_sync(0xffffffffu, sumA, 2);
    sumB += __shfl_xor_sync(0xffffffffu, sumB, 1);
    sumB += __shfl_xor_sync(0xffffffffu, sumB, 2);
    const float invA = 1.0f / sumA;
    const float invB = 1.0f / sumB;

    #pragma unroll
    for (int nn = 0; nn < 4; nn++) {
        const int d = nn * 8 + 2 * tig;
        if (vA) {
            float2 o = make_float2(av[nn][0] * invA, av[nn][1] * invA);
            *(float2*)(g_ao + ((size_t)b * N_TOK + iA) * DIM + h * HD + d) = o;
        }
        if (vB) {
            float2 o = make_float2(av[nn][2] * invB, av[nn][3] * invB);
            *(float2*)(g_ao + ((size_t)b * N_TOK + iB) * DIM + h * HD + d) = o;
        }
    }
}

// ---------------- kernel 2: output projection (R7 best form) ---------------
__global__ __launch_bounds__(256, 2)
void proj_kernel(const float* __restrict__ w,
                 const float* __restrict__ bias,
                 float* __restrict__ out) {
    extern __shared__ float smf[];
    unsigned* xs    = (unsigned*)smf;            // [128][100] tf32 bits
    unsigned* wfrag = (unsigned*)smf + 12800;    // [144][64]
    float*    bs    = smf + 12800 + 9216;        // [96]
    const int tid = threadIdx.x;
    const int m0  = blockIdx.x * 128;

    for (int idx = tid; idx < 12 * 12 * 32; idx += 256) {
        int t = idx >> 5, l = idx & 31;
        int nt = t / 12, kk = t - nt * 12;
        int gl = l >> 2, tl = l & 3;
        int c  = nt * 8 + gl;
        int k0 = kk * 8 + tl;
        wfrag[t * 64 + l * 2]     = f2tf(w[c * 96 + k0]);
        wfrag[t * 64 + l * 2 + 1] = f2tf(w[c * 96 + k0 + 4]);
    }
    if (tid < 96) bs[tid] = bias[tid];
    for (int idx = tid; idx < 128 * 96; idx += 256) {
        int r = idx / 96, c = idx - r * 96;
        xs[r * 100 + c] = f2tf(g_ao[(size_t)m0 * 96 + idx]);
    }
    __syncthreads();

    const int wp   = tid >> 5;
    const int lane = tid & 31;
    const int g    = lane >> 2;
    const int tig  = lane & 3;
    const int cg   = wp & 3;
    const int mh   = wp >> 2;

    uint2 breg[12][3];
    #pragma unroll
    for (int kk = 0; kk < 12; kk++)
        #pragma unroll
        for (int ntl = 0; ntl < 3; ntl++)
            breg[kk][ntl] = *(const uint2*)(wfrag + ((3 * cg + ntl) * 12 + kk) * 64 + lane * 2);

    #pragma unroll
    for (int s = 0; s < 4; s++) {
        const unsigned* xrA = xs + (mh * 64 + s * 16 + g) * 100;
        const unsigned* xrB = xrA + 800;

        float acc[3][4];
        #pragma unroll
        for (int ntl = 0; ntl < 3; ntl++)
            #pragma unroll
            for (int e = 0; e < 4; e++) acc[ntl][e] = 0.f;

        #pragma unroll
        for (int kk = 0; kk < 12; kk++) {
            unsigned a0 = xrA[kk * 8 + tig];
            unsigned a1 = xrB[kk * 8 + tig];
            unsigned a2 = xrA[kk * 8 + tig + 4];
            unsigned a3 = xrB[kk * 8 + tig + 4];
            #pragma unroll
            for (int ntl = 0; ntl < 3; ntl++)
                mma_tf32(acc[ntl][0], acc[ntl][1], acc[ntl][2], acc[ntl][3],
                         a0, a1, a2, a3, breg[kk][ntl].x, breg[kk][ntl].y);
        }

        const size_t mA = m0 + mh * 64 + s * 16 + g;
        const size_t mB = mA + 8;
        #pragma unroll
        for (int ntl = 0; ntl < 3; ntl++) {
            int c0 = (3 * cg + ntl) * 8 + 2 * tig;
            float bb0 = bs[c0], bb1 = bs[c0 + 1];
            *(float2*)(out + mA * 96 + c0) = make_float2(acc[ntl][0] + bb0, acc[ntl][1] + bb1);
            *(float2*)(out + mB * 96 + c0) = make_float2(acc[ntl][2] + bb0, acc[ntl][3] + bb1);
        }
    }
}

// ---------------- launch ---------------------------------------------------
extern "C" void kernel_launch(void* const* d_in, const int* in_sizes, int n_in,
                              void* d_out, int out_size) {
    const float* x      = (const float*)d_in[0];
    const float* mask   = (const float*)d_in[1];
    const float* qkv_w  = (const float*)d_in[2];
    const float* qkv_b  = (const float*)d_in[3];
    const float* proj_w = (const float*)d_in[4];
    const float* proj_b = (const float*)d_in[5];
    const float* rpb    = (const float*)d_in[6];
    const int*   relidx = (const int*)d_in[7];
    float* out = (float*)d_out;

    const int smem_attn = (11264 + 11264 + 9216 + 12800 + 288) * 4;  // 179,328 B
    const int smem_proj = (12800 + 9216 + 96) * 4;                   //  88,448 B
    cudaFuncSetAttribute(attn_kernel, cudaFuncAttributeMaxDynamicSharedMemorySize, smem_attn);
    cudaFuncSetAttribute(proj_kernel, cudaFuncAttributeMaxDynamicSharedMemorySize, smem_proj);

    cb_kernel  <<<dim3(N_TOK, NW * HEADS), 352>>>(mask, rpb, relidx);
    attn_kernel<<<B_TOT * HEADS, 704, smem_attn>>>(x, qkv_w, qkv_b);
    proj_kernel<<<1372, 256, smem_proj>>>(proj_w, proj_b, out);
    (void)in_sizes; (void)n_in; (void)out_size;
}

// round 10
// speedup vs baseline: 1.1280x; 1.0641x over previous
#include <cuda_runtime.h>
#include <math.h>

#define B_TOT 512
#define N_TOK 343
#define DIM   96
#define HEADS 3
#define HD    32
#define NW    64
#define CB_STRIDE 344
#define CB_SLICE  (N_TOK * CB_STRIDE)   // 117992

// ---------------- scratch (device globals: no allocation allowed) ----------
__device__ float g_ao[(size_t)B_TOT * N_TOK * DIM];          // [B][N][H*hd]
__device__ float g_cb[(size_t)NW * HEADS * CB_SLICE + 64];   // (mask+bias)*log2e

// ---------------- helpers --------------------------------------------------
__device__ __forceinline__ float ex2f(float x) {
    float r;
    asm("ex2.approx.f32 %0, %1;" : "=f"(r) : "f"(x));
    return r;
}

__device__ __forceinline__ unsigned f2tf(float x) {
    unsigned r;
    asm("cvt.rna.tf32.f32 %0, %1;" : "=r"(r) : "f"(x));
    return r;
}

__device__ __forceinline__ void mma_tf32(float& c0, float& c1, float& c2, float& c3,
                                         unsigned a0, unsigned a1, unsigned a2, unsigned a3,
                                         unsigned b0, unsigned b1) {
    asm volatile("mma.sync.aligned.m16n8k8.row.col.f32.tf32.tf32.f32 "
                 "{%0,%1,%2,%3}, {%4,%5,%6,%7}, {%8,%9}, {%0,%1,%2,%3};"
                 : "+f"(c0), "+f"(c1), "+f"(c2), "+f"(c3)
                 : "r"(a0), "r"(a1), "r"(a2), "r"(a3), "r"(b0), "r"(b1));
}

// kfrag word index for K value at (row n, col d)
__device__ __forceinline__ int kpos(int n, int d) {
    return (((n >> 3) * 4 + (d >> 3)) << 6) + (((n & 7) << 2) | (d & 3)) * 2 + ((d & 7) >> 2);
}
// vfrag word index for V value at (row j, col d)
__device__ __forceinline__ int vpos(int j, int d) {
    return (((j >> 3) * 4 + (d >> 3)) << 6) + (((d & 7) << 2) | (j & 3)) * 2 + ((j & 7) >> 2);
}

// ---------------- kernel 0: combined bias table, pre-scaled by log2e -------
__global__ __launch_bounds__(352)
void cb_kernel(const float* __restrict__ mask,
               const float* __restrict__ rpb,
               const int*   __restrict__ relidx) {
    const int i  = blockIdx.x;
    const int wh = blockIdx.y;
    const int w  = wh / HEADS;
    const int h  = wh - w * HEADS;
    const int j  = threadIdx.x;
    if (j < N_TOK) {
        int rel = relidx[i * N_TOK + j];
        g_cb[(size_t)wh * CB_SLICE + i * CB_STRIDE + j] =
            (mask[(size_t)w * N_TOK * N_TOK + i * N_TOK + j] + rpb[rel * HEADS + h])
            * 1.4426950408889634f;
    }
}

// ---------------- kernel 1: FUSED qkv + attention --------------------------
// One CTA = (window, head). Prologue computes K,V directly into B-fragment
// smem layouts and per-warp Q A-fragments (shfl reshape). Q carries
// 1/sqrt(hd) * log2e so softmax numerator is ex2(c + cb): 2 instr per exp.
__global__ __launch_bounds__(704, 1)
void attn_kernel(const float* __restrict__ xg,
                 const float* __restrict__ qkvw,
                 const float* __restrict__ qkvb) {
    extern __shared__ unsigned smu[];
    unsigned* kfrag = smu;               // [44*4][64] : 11264
    unsigned* vfrag = smu + 11264;       // [44*4][64] : 11264
    unsigned* wf    = smu + 22528;       // [3][4][12][64] : 9216
    unsigned* xs    = smu + 31744;       // [128][100] tf32 bits : 12800
    float*    bsm   = (float*)(smu + 44544);   // [288]

    const int bid  = blockIdx.x;
    const int wh   = bid >> 3;                 // window*3 + h
    const int rep  = bid & 7;
    const int win  = wh / HEADS;
    const int h    = wh - win * HEADS;
    const int b    = rep * NW + win;
    const int tid  = threadIdx.x;
    const int lane = tid & 31;
    const int w    = tid >> 5;           // 0..21
    const int g    = lane >> 2;          // 0..7
    const int tig  = lane & 3;           // 0..3

    const float* xrow0 = xg + (size_t)b * N_TOK * DIM;
    const float* cbp   = g_cb + (size_t)wh * CB_SLICE;
    const float qscale = 0.17677669529663687f * 1.4426950408889634f;  // /sqrt(32) * log2e

    // ---- stage weight B-fragments for this head ----
    for (int idx = tid; idx < 3 * 4 * 12 * 32; idx += 704) {
        int t = idx >> 5, l = idx & 31;
        int third = t / 48, rem = t - third * 48;
        int nt = rem / 12, kk = rem - nt * 12;
        int gl = l >> 2, tl = l & 3;
        int c  = third * 96 + h * 32 + nt * 8 + gl;
        int k0 = kk * 8 + tl;
        wf[t * 64 + l * 2]     = f2tf(qkvw[c * 96 + k0]);
        wf[t * 64 + l * 2 + 1] = f2tf(qkvw[c * 96 + k0 + 4]);
    }
    for (int idx = tid; idx < 96; idx += 704) {
        bsm[idx] = qkvb[idx + h * 32 + ((idx >> 5) * 64)];  // bsm[third*32+cc] = qkvb[third*96+h*32+cc]
    }

    unsigned qa[4][4];   // Q A-fragments, filled during the owning chunk

    // ---- chunks of 128 rows: compute K,V into frags; Q for owning warps ----
    #pragma unroll 1
    for (int c = 0; c < 3; c++) {
        if (c > 0) __syncthreads();
        for (int idx = tid; idx < 128 * 96; idx += 704) {
            int r = idx / 96, cc = idx - r * 96;
            int n = 128 * c + r;
            float v = (n < N_TOK) ? xrow0[(size_t)n * 96 + cc] : 0.f;
            xs[r * 100 + cc] = f2tf(v);
        }
        __syncthreads();

        // K/V units: u = (s<<2) | (third01<<1) | nhalf, 32 units over 22 warps
        for (int u = w; u < 32; u += 22) {
            int s = u >> 2, th = (u >> 1) & 1, nh = u & 1;
            const unsigned* xrA = xs + (s * 16 + g) * 100;
            const unsigned* xrB = xrA + 800;
            #pragma unroll
            for (int ntl = 0; ntl < 2; ntl++) {
                int nt = nh * 2 + ntl;
                float a0f = 0.f, a1f = 0.f, a2f = 0.f, a3f = 0.f;
                #pragma unroll
                for (int kk = 0; kk < 12; kk++) {
                    unsigned a0 = xrA[kk * 8 + tig];
                    unsigned a1 = xrB[kk * 8 + tig];
                    unsigned a2 = xrA[kk * 8 + tig + 4];
                    unsigned a3 = xrB[kk * 8 + tig + 4];
                    uint2 bb = *(const uint2*)(wf + (((th + 1) * 48) + nt * 12 + kk) * 64 + lane * 2);
                    mma_tf32(a0f, a1f, a2f, a3f, a0, a1, a2, a3, bb.x, bb.y);
                }
                int c0 = nt * 8 + 2 * tig;
                float b0 = bsm[(th + 1) * 32 + c0];
                float b1 = bsm[(th + 1) * 32 + c0 + 1];
                int nA = 128 * c + s * 16 + g;
                int nB = nA + 8;
                float v00 = a0f + b0, v01 = a1f + b1;    // row nA
                float v10 = a2f + b0, v11 = a3f + b1;    // row nB
                if (th == 0) {
                    if (nA < 352) {
                        kfrag[kpos(nA, c0)]     = f2tf(v00);
                        kfrag[kpos(nA, c0 + 1)] = f2tf(v01);
                    }
                    if (nB < 352) {
                        kfrag[kpos(nB, c0)]     = f2tf(v10);
                        kfrag[kpos(nB, c0 + 1)] = f2tf(v11);
                    }
                } else {
                    if (nA < 352) {
                        vfrag[vpos(nA, c0)]     = f2tf(v00);
                        vfrag[vpos(nA, c0 + 1)] = f2tf(v01);
                    }
                    if (nB < 352) {
                        vfrag[vpos(nB, c0)]     = f2tf(v10);
                        vfrag[vpos(nB, c0 + 1)] = f2tf(v11);
                    }
                }
            }
        }

        // Q for warps whose stripe lives in this chunk (stripe w: rows 16w..16w+15)
        if ((w >> 3) == c) {
            const int s = w & 7;
            const int srcq0 = (lane & ~3) | (tig >> 1);
            const int srcq1 = srcq0 + 2;
            const bool oddt = tig & 1;
            const unsigned* xrA = xs + (s * 16 + g) * 100;
            const unsigned* xrB = xrA + 800;
            #pragma unroll
            for (int nt = 0; nt < 4; nt++) {
                float a0f = 0.f, a1f = 0.f, a2f = 0.f, a3f = 0.f;
                #pragma unroll
                for (int kk = 0; kk < 12; kk++) {
                    unsigned a0 = xrA[kk * 8 + tig];
                    unsigned a1 = xrB[kk * 8 + tig];
                    unsigned a2 = xrA[kk * 8 + tig + 4];
                    unsigned a3 = xrB[kk * 8 + tig + 4];
                    uint2 bb = *(const uint2*)(wf + (nt * 12 + kk) * 64 + lane * 2);
                    mma_tf32(a0f, a1f, a2f, a3f, a0, a1, a2, a3, bb.x, bb.y);
                }
                int c0 = nt * 8 + 2 * tig;
                float b0 = bsm[c0], b1 = bsm[c0 + 1];
                unsigned t0 = f2tf((a0f + b0) * qscale);
                unsigned t1 = f2tf((a1f + b1) * qscale);
                unsigned t2 = f2tf((a2f + b0) * qscale);
                unsigned t3 = f2tf((a3f + b1) * qscale);
                unsigned u0 = __shfl_sync(0xffffffffu, t0, srcq0);
                unsigned u1 = __shfl_sync(0xffffffffu, t1, srcq0);
                unsigned u2 = __shfl_sync(0xffffffffu, t2, srcq0);
                unsigned u3 = __shfl_sync(0xffffffffu, t3, srcq0);
                unsigned w0 = __shfl_sync(0xffffffffu, t0, srcq1);
                unsigned w1 = __shfl_sync(0xffffffffu, t1, srcq1);
                unsigned w2 = __shfl_sync(0xffffffffu, t2, srcq1);
                unsigned w3 = __shfl_sync(0xffffffffu, t3, srcq1);
                qa[nt][0] = oddt ? u1 : u0;
                qa[nt][1] = oddt ? u3 : u2;
                qa[nt][2] = oddt ? w1 : w0;
                qa[nt][3] = oddt ? w3 : w2;
            }
        }
    }
    __syncthreads();

    // ---- mainloop ----
    const int i0 = w * 16;
    const int iA = i0 + g, iB = i0 + g + 8;
    const bool vA = (iA < N_TOK), vB = (iB < N_TOK);
    const int srcq0 = (lane & ~3) | (tig >> 1);
    const int srcq1 = srcq0 + 2;
    const bool oddt = tig & 1;

    float av[4][4];
    #pragma unroll
    for (int nn = 0; nn < 4; nn++)
        #pragma unroll
        for (int e = 0; e < 4; e++) av[nn][e] = 0.f;

    float sumA = 0.f, sumB = 0.f;
    const float* cbA = cbp + (size_t)iA * CB_STRIDE;
    const float* cbB = cbp + (size_t)iB * CB_STRIDE;

    // cb double buffer: load pair 0 before the loop
    float cbq[2][4];
    #pragma unroll
    for (int tt = 0; tt < 2; tt++) {
        const int j0 = tt * 8 + 2 * tig;
        float c00, c01, c10, c11;
        if (vA) { float2 t = *(const float2*)(cbA + j0); c00 = t.x; c01 = t.y; }
        else    { c00 = c01 = -1e30f; }
        if (vB) { float2 t = *(const float2*)(cbB + j0); c10 = t.x; c11 = t.y; }
        else    { c10 = c11 = -1e30f; }
        cbq[tt][0] = c00; cbq[tt][1] = c01; cbq[tt][2] = c10; cbq[tt][3] = c11;
    }

    #pragma unroll 1
    for (int tp = 0; tp < 22; tp++) {
        // ---- prefetch cb for next tile pair ----
        float cbn[2][4];
        if (tp < 21) {
            #pragma unroll
            for (int tt = 0; tt < 2; tt++) {
                const int j0 = (2 * (tp + 1) + tt) * 8 + 2 * tig;
                float c00, c01, c10, c11;
                if (vA && j0 < N_TOK) { float2 t = *(const float2*)(cbA + j0); c00 = t.x; c01 = t.y; }
                else                  { c00 = c01 = -1e30f; }
                if (vB && j0 < N_TOK) { float2 t = *(const float2*)(cbB + j0); c10 = t.x; c11 = t.y; }
                else                  { c10 = c11 = -1e30f; }
                if (j0 + 1 >= N_TOK)  { c01 = -1e30f; c11 = -1e30f; }
                cbn[tt][0] = c00; cbn[tt][1] = c01; cbn[tt][2] = c10; cbn[tt][3] = c11;
            }
        }

        // ---- QK mma, two independent chains ----
        float c[2][4];
        #pragma unroll
        for (int tt = 0; tt < 2; tt++) {
            c[tt][0] = c[tt][1] = c[tt][2] = c[tt][3] = 0.f;
            const int ntg = 2 * tp + tt;
            #pragma unroll
            for (int kk = 0; kk < 4; kk++) {
                uint2 bb = *(const uint2*)(kfrag + (ntg * 4 + kk) * 64 + lane * 2);
                mma_tf32(c[tt][0], c[tt][1], c[tt][2], c[tt][3],
                         qa[kk][0], qa[kk][1], qa[kk][2], qa[kk][3], bb.x, bb.y);
            }
        }

        // ---- exp via ex2.approx: scores already in log2 domain ----
        float p[2][4];
        #pragma unroll
        for (int tt = 0; tt < 2; tt++) {
            p[tt][0] = ex2f(c[tt][0] + cbq[tt][0]);
            p[tt][1] = ex2f(c[tt][1] + cbq[tt][1]);
            p[tt][2] = ex2f(c[tt][2] + cbq[tt][2]);
            p[tt][3] = ex2f(c[tt][3] + cbq[tt][3]);
            sumA += p[tt][0] + p[tt][1];
            sumB += p[tt][2] + p[tt][3];
        }

        // ---- reshape C-frag -> A-frag ----
        unsigned af[2][4];
        #pragma unroll
        for (int tt = 0; tt < 2; tt++) {
            unsigned t0 = f2tf(p[tt][0]), t1 = f2tf(p[tt][1]);
            unsigned t2 = f2tf(p[tt][2]), t3 = f2tf(p[tt][3]);
            unsigned u0 = __shfl_sync(0xffffffffu, t0, srcq0);
            unsigned u1 = __shfl_sync(0xffffffffu, t1, srcq0);
            unsigned u2 = __shfl_sync(0xffffffffu, t2, srcq0);
            unsigned u3 = __shfl_sync(0xffffffffu, t3, srcq0);
            unsigned w0 = __shfl_sync(0xffffffffu, t0, srcq1);
            unsigned w1 = __shfl_sync(0xffffffffu, t1, srcq1);
            unsigned w2 = __shfl_sync(0xffffffffu, t2, srcq1);
            unsigned w3 = __shfl_sync(0xffffffffu, t3, srcq1);
            af[tt][0] = oddt ? u1 : u0;
            af[tt][1] = oddt ? u3 : u2;
            af[tt][2] = oddt ? w1 : w0;
            af[tt][3] = oddt ? w3 : w2;
        }

        // ---- AV mma ----
        #pragma unroll
        for (int tt = 0; tt < 2; tt++) {
            const int ntg = 2 * tp + tt;
            #pragma unroll
            for (int nn = 0; nn < 4; nn++) {
                uint2 bb = *(const uint2*)(vfrag + (ntg * 4 + nn) * 64 + lane * 2);
                mma_tf32(av[nn][0], av[nn][1], av[nn][2], av[nn][3],
                         af[tt][0], af[tt][1], af[tt][2], af[tt][3], bb.x, bb.y);
            }
        }

        if (tp < 21) {
            #pragma unroll
            for (int tt = 0; tt < 2; tt++)
                #pragma unroll
                for (int e = 0; e < 4; e++) cbq[tt][e] = cbn[tt][e];
        }
    }

    sumA += __shfl_xor_sync(0xffffffffu, sumA, 1);
    sumA += __shfl_xor_sync(0xffffffffu, sumA, 2);
    sumB += __shfl_xor_sync(0xffffffffu, sumB, 1);
    sumB += __shfl_xor_sync(0xffffffffu, sumB, 2);
    const float invA = 1.0f / sumA;
    const float invB = 1.0f / sumB;

    #pragma unroll
    for (int nn = 0; nn < 4; nn++) {
        const int d = nn * 8 + 2 * tig;
        if (vA) {
            float2 o = make_float2(av[nn][0] * invA, av[nn][1] * invA);
            *(float2*)(g_ao + ((size_t)b * N_TOK + iA) * DIM + h * HD + d) = o;
        }
        if (vB) {
            float2 o = make_float2(av[nn][2] * invB, av[nn][3] * invB);
            *(float2*)(g_ao + ((size_t)b * N_TOK + iB) * DIM + h * HD + d) = o;
        }
    }
}

// ---------------- kernel 2: output projection ------------------------------
__global__ __launch_bounds__(256, 2)
void proj_kernel(const float* __restrict__ w,
                 const float* __restrict__ bias,
                 float* __restrict__ out) {
    extern __shared__ float smf[];
    unsigned* xs    = (unsigned*)smf;            // [128][100] tf32 bits
    unsigned* wfrag = (unsigned*)smf + 12800;    // [144][64]
    float*    bs    = smf + 12800 + 9216;        // [96]
    const int tid = threadIdx.x;
    const int m0  = blockIdx.x * 128;

    for (int idx = tid; idx < 12 * 12 * 32; idx += 256) {
        int t = idx >> 5, l = idx & 31;
        int nt = t / 12, kk = t - nt * 12;
        int gl = l >> 2, tl = l & 3;
        int c  = nt * 8 + gl;
        int k0 = kk * 8 + tl;
        wfrag[t * 64 + l * 2]     = f2tf(w[c * 96 + k0]);
        wfrag[t * 64 + l * 2 + 1] = f2tf(w[c * 96 + k0 + 4]);
    }
    if (tid < 96) bs[tid] = bias[tid];
    for (int idx = tid; idx < 128 * 96; idx += 256) {
        int r = idx / 96, c = idx - r * 96;
        xs[r * 100 + c] = f2tf(g_ao[(size_t)m0 * 96 + idx]);
    }
    __syncthreads();

    const int wp   = tid >> 5;
    const int lane = tid & 31;
    const int g    = lane >> 2;
    const int tig  = lane & 3;
    const int cg   = wp & 3;
    const int mh   = wp >> 2;

    uint2 breg[12][3];
    #pragma unroll
    for (int kk = 0; kk < 12; kk++)
        #pragma unroll
        for (int ntl = 0; ntl < 3; ntl++)
            breg[kk][ntl] = *(const uint2*)(wfrag + ((3 * cg + ntl) * 12 + kk) * 64 + lane * 2);

    #pragma unroll
    for (int s = 0; s < 4; s++) {
        const unsigned* xrA = xs + (mh * 64 + s * 16 + g) * 100;
        const unsigned* xrB = xrA + 800;

        float acc[3][4];
        #pragma unroll
        for (int ntl = 0; ntl < 3; ntl++)
            #pragma unroll
            for (int e = 0; e < 4; e++) acc[ntl][e] = 0.f;

        #pragma unroll
        for (int kk = 0; kk < 12; kk++) {
            unsigned a0 = xrA[kk * 8 + tig];
            unsigned a1 = xrB[kk * 8 + tig];
            unsigned a2 = xrA[kk * 8 + tig + 4];
            unsigned a3 = xrB[kk * 8 + tig + 4];
            #pragma unroll
            for (int ntl = 0; ntl < 3; ntl++)
                mma_tf32(acc[ntl][0], acc[ntl][1], acc[ntl][2], acc[ntl][3],
                         a0, a1, a2, a3, breg[kk][ntl].x, breg[kk][ntl].y);
        }

        const size_t mA = m0 + mh * 64 + s * 16 + g;
        const size_t mB = mA + 8;
        #pragma unroll
        for (int ntl = 0; ntl < 3; ntl++) {
            int c0 = (3 * cg + ntl) * 8 + 2 * tig;
            float bb0 = bs[c0], bb1 = bs[c0 + 1];
            *(float2*)(out + mA * 96 + c0) = make_float2(acc[ntl][0] + bb0, acc[ntl][1] + bb1);
            *(float2*)(out + mB * 96 + c0) = make_float2(acc[ntl][2] + bb0, acc[ntl][3] + bb1);
        }
    }
}

// ---------------- launch ---------------------------------------------------
extern "C" void kernel_launch(void* const* d_in, const int* in_sizes, int n_in,
                              void* d_out, int out_size) {
    const float* x      = (const float*)d_in[0];
    const float* mask   = (const float*)d_in[1];
    const float* qkv_w  = (const float*)d_in[2];
    const float* qkv_b  = (const float*)d_in[3];
    const float* proj_w = (const float*)d_in[4];
    const float* proj_b = (const float*)d_in[5];
    const float* rpb    = (const float*)d_in[6];
    const int*   relidx = (const int*)d_in[7];
    float* out = (float*)d_out;

    const int smem_attn = (11264 + 11264 + 9216 + 12800 + 288) * 4;  // 179,328 B
    const int smem_proj = (12800 + 9216 + 96) * 4;                   //  88,448 B
    cudaFuncSetAttribute(attn_kernel, cudaFuncAttributeMaxDynamicSharedMemorySize, smem_attn);
    cudaFuncSetAttribute(proj_kernel, cudaFuncAttributeMaxDynamicSharedMemorySize, smem_proj);

    cb_kernel  <<<dim3(N_TOK, NW * HEADS), 352>>>(mask, rpb, relidx);
    attn_kernel<<<B_TOT * HEADS, 704, smem_attn>>>(x, qkv_w, qkv_b);
    proj_kernel<<<1372, 256, smem_proj>>>(proj_w, proj_b, out);
    (void)in_sizes; (void)n_in; (void)out_size;
}

// round 11
// speedup vs baseline: 1.2266x; 1.0874x over previous
#include <cuda_runtime.h>
#include <cuda_fp16.h>
#include <math.h>

#define B_TOT 512
#define N_TOK 343
#define DIM   96
#define HEADS 3
#define HD    32
#define NW    64
#define CB_STRIDE 344
#define CB_SLICE  (N_TOK * CB_STRIDE)   // 117992

// ---------------- scratch (device globals: no allocation allowed) ----------
__device__ float g_ao[(size_t)B_TOT * N_TOK * DIM];          // [B][N][H*hd]
__device__ float g_cb[(size_t)NW * HEADS * CB_SLICE + 64];   // (mask+bias)*log2e

// ---------------- helpers --------------------------------------------------
__device__ __forceinline__ float ex2f(float x) {
    float r;
    asm("ex2.approx.f32 %0, %1;" : "=f"(r) : "f"(x));
    return r;
}

__device__ __forceinline__ unsigned f2tf(float x) {
    unsigned r;
    asm("cvt.rna.tf32.f32 %0, %1;" : "=r"(r) : "f"(x));
    return r;
}

// pack two f32 into f16x2: lo -> lower half, hi -> upper half
__device__ __forceinline__ unsigned pack_f16(float lo, float hi) {
    unsigned d;
    asm("cvt.rn.f16x2.f32 %0, %1, %2;" : "=r"(d) : "f"(hi), "f"(lo));
    return d;
}

__device__ __forceinline__ void mma_tf32(float& c0, float& c1, float& c2, float& c3,
                                         unsigned a0, unsigned a1, unsigned a2, unsigned a3,
                                         unsigned b0, unsigned b1) {
    asm volatile("mma.sync.aligned.m16n8k8.row.col.f32.tf32.tf32.f32 "
                 "{%0,%1,%2,%3}, {%4,%5,%6,%7}, {%8,%9}, {%0,%1,%2,%3};"
                 : "+f"(c0), "+f"(c1), "+f"(c2), "+f"(c3)
                 : "r"(a0), "r"(a1), "r"(a2), "r"(a3), "r"(b0), "r"(b1));
}

__device__ __forceinline__ void mma_f16(float& c0, float& c1, float& c2, float& c3,
                                        unsigned a0, unsigned a1, unsigned a2, unsigned a3,
                                        unsigned b0, unsigned b1) {
    asm volatile("mma.sync.aligned.m16n8k16.row.col.f32.f16.f16.f32 "
                 "{%0,%1,%2,%3}, {%4,%5,%6,%7}, {%8,%9}, {%0,%1,%2,%3};"
                 : "+f"(c0), "+f"(c1), "+f"(c2), "+f"(c3)
                 : "r"(a0), "r"(a1), "r"(a2), "r"(a3), "r"(b0), "r"(b1));
}

// kfrag word index for K value at (row n, col d)  (tf32 m16n8k8 B layout)
__device__ __forceinline__ int kpos(int n, int d) {
    return (((n >> 3) * 4 + (d >> 3)) << 6) + (((n & 7) << 2) | (d & 3)) * 2 + ((d & 7) >> 2);
}
// vfrag HALF index for V value at (row j, col d)  (fp16 m16n8k16 B layout)
// tile = (j>>4, d>>3); within: lane = (d&7)*4 + ((j>>1)&3), reg = (j>>3)&1, half = j&1
__device__ __forceinline__ int vhpos(int j, int d) {
    return (((j >> 4) * 4 + (d >> 3)) << 7)
         + (((d & 7) * 4 + ((j >> 1) & 3)) << 2) + (((j >> 3) & 1) << 1) + (j & 1);
}

// ---------------- kernel 0: combined bias table, pre-scaled by log2e -------
__global__ __launch_bounds__(352)
void cb_kernel(const float* __restrict__ mask,
               const float* __restrict__ rpb,
               const int*   __restrict__ relidx) {
    const int i  = blockIdx.x;
    const int wh = blockIdx.y;
    const int w  = wh / HEADS;
    const int h  = wh - w * HEADS;
    const int j  = threadIdx.x;
    if (j < N_TOK) {
        int rel = relidx[i * N_TOK + j];
        g_cb[(size_t)wh * CB_SLICE + i * CB_STRIDE + j] =
            (mask[(size_t)w * N_TOK * N_TOK + i * N_TOK + j] + rpb[rel * HEADS + h])
            * 1.4426950408889634f;
    }
}

// ---------------- kernel 1: FUSED qkv + attention --------------------------
// One CTA = (window, head). Prologue computes K (tf32 B-frags) and V (fp16
// B-frags) directly into smem, and per-warp Q A-fragments. Mainloop per
// tile-pair: QK tf32 mma -> ex2 -> cvt-to-f16x2 (C-frag IS the k16 A-frag;
// no shuffles) -> one fp16 m16n8k16 AV mma per nn.
__global__ __launch_bounds__(704, 1)
void attn_kernel(const float* __restrict__ xg,
                 const float* __restrict__ qkvw,
                 const float* __restrict__ qkvb) {
    extern __shared__ unsigned smu[];
    unsigned* kfrag = smu;               // [44*4][64] tf32        : 11264 words
    unsigned* vfrag = smu + 11264;       // [22*4][64] f16x2       :  5632 words
    unsigned* wf    = smu + 16896;       // [3][4][12][64]         :  9216 words
    unsigned* xs    = smu + 26112;       // [128][100] tf32 bits   : 12800 words
    float*    bsm   = (float*)(smu + 38912);   // [288]
    __half*   vh    = (__half*)vfrag;

    const int bid  = blockIdx.x;
    const int wh   = bid >> 3;                 // window*3 + h
    const int rep  = bid & 7;
    const int win  = wh / HEADS;
    const int h    = wh - win * HEADS;
    const int b    = rep * NW + win;
    const int tid  = threadIdx.x;
    const int lane = tid & 31;
    const int w    = tid >> 5;           // 0..21
    const int g    = lane >> 2;          // 0..7
    const int tig  = lane & 3;           // 0..3

    const float* xrow0 = xg + (size_t)b * N_TOK * DIM;
    const float* cbp   = g_cb + (size_t)wh * CB_SLICE;
    const float qscale = 0.17677669529663687f * 1.4426950408889634f;  // /sqrt(32) * log2e

    // ---- stage weight B-fragments for this head ----
    for (int idx = tid; idx < 3 * 4 * 12 * 32; idx += 704) {
        int t = idx >> 5, l = idx & 31;
        int third = t / 48, rem = t - third * 48;
        int nt = rem / 12, kk = rem - nt * 12;
        int gl = l >> 2, tl = l & 3;
        int c  = third * 96 + h * 32 + nt * 8 + gl;
        int k0 = kk * 8 + tl;
        wf[t * 64 + l * 2]     = f2tf(qkvw[c * 96 + k0]);
        wf[t * 64 + l * 2 + 1] = f2tf(qkvw[c * 96 + k0 + 4]);
    }
    for (int idx = tid; idx < 96; idx += 704) {
        bsm[idx] = qkvb[idx + h * 32 + ((idx >> 5) * 64)];  // bsm[third*32+cc] = qkvb[third*96+h*32+cc]
    }

    unsigned qa[4][4];   // Q A-fragments, filled during the owning chunk

    // ---- chunks of 128 rows: compute K,V into frags; Q for owning warps ----
    #pragma unroll 1
    for (int c = 0; c < 3; c++) {
        if (c > 0) __syncthreads();
        for (int idx = tid; idx < 128 * 96; idx += 704) {
            int r = idx / 96, cc = idx - r * 96;
            int n = 128 * c + r;
            float v = (n < N_TOK) ? xrow0[(size_t)n * 96 + cc] : 0.f;
            xs[r * 100 + cc] = f2tf(v);
        }
        __syncthreads();

        // K/V units: u = (s<<2) | (third01<<1) | nhalf, 32 units over 22 warps
        for (int u = w; u < 32; u += 22) {
            int s = u >> 2, th = (u >> 1) & 1, nh = u & 1;
            const unsigned* xrA = xs + (s * 16 + g) * 100;
            const unsigned* xrB = xrA + 800;
            #pragma unroll
            for (int ntl = 0; ntl < 2; ntl++) {
                int nt = nh * 2 + ntl;
                float a0f = 0.f, a1f = 0.f, a2f = 0.f, a3f = 0.f;
                #pragma unroll
                for (int kk = 0; kk < 12; kk++) {
                    unsigned a0 = xrA[kk * 8 + tig];
                    unsigned a1 = xrB[kk * 8 + tig];
                    unsigned a2 = xrA[kk * 8 + tig + 4];
                    unsigned a3 = xrB[kk * 8 + tig + 4];
                    uint2 bb = *(const uint2*)(wf + (((th + 1) * 48) + nt * 12 + kk) * 64 + lane * 2);
                    mma_tf32(a0f, a1f, a2f, a3f, a0, a1, a2, a3, bb.x, bb.y);
                }
                int c0 = nt * 8 + 2 * tig;
                float b0 = bsm[(th + 1) * 32 + c0];
                float b1 = bsm[(th + 1) * 32 + c0 + 1];
                int nA = 128 * c + s * 16 + g;
                int nB = nA + 8;
                float v00 = a0f + b0, v01 = a1f + b1;    // row nA
                float v10 = a2f + b0, v11 = a3f + b1;    // row nB
                if (th == 0) {
                    if (nA < 352) {
                        kfrag[kpos(nA, c0)]     = f2tf(v00);
                        kfrag[kpos(nA, c0 + 1)] = f2tf(v01);
                    }
                    if (nB < 352) {
                        kfrag[kpos(nB, c0)]     = f2tf(v10);
                        kfrag[kpos(nB, c0 + 1)] = f2tf(v11);
                    }
                } else {
                    if (nA < 352) {
                        vh[vhpos(nA, c0)]     = __float2half_rn(v00);
                        vh[vhpos(nA, c0 + 1)] = __float2half_rn(v01);
                    }
                    if (nB < 352) {
                        vh[vhpos(nB, c0)]     = __float2half_rn(v10);
                        vh[vhpos(nB, c0 + 1)] = __float2half_rn(v11);
                    }
                }
            }
        }

        // Q for warps whose stripe lives in this chunk (stripe w: rows 16w..16w+15)
        if ((w >> 3) == c) {
            const int s = w & 7;
            const int srcq0 = (lane & ~3) | (tig >> 1);
            const int srcq1 = srcq0 + 2;
            const bool oddt = tig & 1;
            const unsigned* xrA = xs + (s * 16 + g) * 100;
            const unsigned* xrB = xrA + 800;
            #pragma unroll
            for (int nt = 0; nt < 4; nt++) {
                float a0f = 0.f, a1f = 0.f, a2f = 0.f, a3f = 0.f;
                #pragma unroll
                for (int kk = 0; kk < 12; kk++) {
                    unsigned a0 = xrA[kk * 8 + tig];
                    unsigned a1 = xrB[kk * 8 + tig];
                    unsigned a2 = xrA[kk * 8 + tig + 4];
                    unsigned a3 = xrB[kk * 8 + tig + 4];
                    uint2 bb = *(const uint2*)(wf + (nt * 12 + kk) * 64 + lane * 2);
                    mma_tf32(a0f, a1f, a2f, a3f, a0, a1, a2, a3, bb.x, bb.y);
                }
                int c0 = nt * 8 + 2 * tig;
                float b0 = bsm[c0], b1 = bsm[c0 + 1];
                unsigned t0 = f2tf((a0f + b0) * qscale);
                unsigned t1 = f2tf((a1f + b1) * qscale);
                unsigned t2 = f2tf((a2f + b0) * qscale);
                unsigned t3 = f2tf((a3f + b1) * qscale);
                unsigned u0 = __shfl_sync(0xffffffffu, t0, srcq0);
                unsigned u1 = __shfl_sync(0xffffffffu, t1, srcq0);
                unsigned u2 = __shfl_sync(0xffffffffu, t2, srcq0);
                unsigned u3 = __shfl_sync(0xffffffffu, t3, srcq0);
                unsigned w0 = __shfl_sync(0xffffffffu, t0, srcq1);
                unsigned w1 = __shfl_sync(0xffffffffu, t1, srcq1);
                unsigned w2 = __shfl_sync(0xffffffffu, t2, srcq1);
                unsigned w3 = __shfl_sync(0xffffffffu, t3, srcq1);
                qa[nt][0] = oddt ? u1 : u0;
                qa[nt][1] = oddt ? u3 : u2;
                qa[nt][2] = oddt ? w1 : w0;
                qa[nt][3] = oddt ? w3 : w2;
            }
        }
    }
    __syncthreads();

    // ---- mainloop ----
    const int i0 = w * 16;
    const int iA = i0 + g, iB = i0 + g + 8;
    const bool vA = (iA < N_TOK), vB = (iB < N_TOK);

    float av[4][4];
    #pragma unroll
    for (int nn = 0; nn < 4; nn++)
        #pragma unroll
        for (int e = 0; e < 4; e++) av[nn][e] = 0.f;

    float sumA = 0.f, sumB = 0.f;
    const float* cbA = cbp + (size_t)iA * CB_STRIDE;
    const float* cbB = cbp + (size_t)iB * CB_STRIDE;

    // cb double buffer: load pair 0 before the loop
    float cbq[2][4];
    #pragma unroll
    for (int tt = 0; tt < 2; tt++) {
        const int j0 = tt * 8 + 2 * tig;
        float c00, c01, c10, c11;
        if (vA) { float2 t = *(const float2*)(cbA + j0); c00 = t.x; c01 = t.y; }
        else    { c00 = c01 = -1e30f; }
        if (vB) { float2 t = *(const float2*)(cbB + j0); c10 = t.x; c11 = t.y; }
        else    { c10 = c11 = -1e30f; }
        cbq[tt][0] = c00; cbq[tt][1] = c01; cbq[tt][2] = c10; cbq[tt][3] = c11;
    }

    #pragma unroll 1
    for (int tp = 0; tp < 22; tp++) {
        // ---- prefetch cb for next tile pair ----
        float cbn[2][4];
        if (tp < 21) {
            #pragma unroll
            for (int tt = 0; tt < 2; tt++) {
                const int j0 = (2 * (tp + 1) + tt) * 8 + 2 * tig;
                float c00, c01, c10, c11;
                if (vA && j0 < N_TOK) { float2 t = *(const float2*)(cbA + j0); c00 = t.x; c01 = t.y; }
                else                  { c00 = c01 = -1e30f; }
                if (vB && j0 < N_TOK) { float2 t = *(const float2*)(cbB + j0); c10 = t.x; c11 = t.y; }
                else                  { c10 = c11 = -1e30f; }
                if (j0 + 1 >= N_TOK)  { c01 = -1e30f; c11 = -1e30f; }
                cbn[tt][0] = c00; cbn[tt][1] = c01; cbn[tt][2] = c10; cbn[tt][3] = c11;
            }
        }

        // ---- QK mma, two independent chains ----
        float c[2][4];
        #pragma unroll
        for (int tt = 0; tt < 2; tt++) {
            c[tt][0] = c[tt][1] = c[tt][2] = c[tt][3] = 0.f;
            const int ntg = 2 * tp + tt;
            #pragma unroll
            for (int kk = 0; kk < 4; kk++) {
                uint2 bb = *(const uint2*)(kfrag + (ntg * 4 + kk) * 64 + lane * 2);
                mma_tf32(c[tt][0], c[tt][1], c[tt][2], c[tt][3],
                         qa[kk][0], qa[kk][1], qa[kk][2], qa[kk][3], bb.x, bb.y);
            }
        }

        // ---- exp via ex2.approx (log2-domain scores) ----
        float p[2][4];
        #pragma unroll
        for (int tt = 0; tt < 2; tt++) {
            p[tt][0] = ex2f(c[tt][0] + cbq[tt][0]);
            p[tt][1] = ex2f(c[tt][1] + cbq[tt][1]);
            p[tt][2] = ex2f(c[tt][2] + cbq[tt][2]);
            p[tt][3] = ex2f(c[tt][3] + cbq[tt][3]);
            sumA += p[tt][0] + p[tt][1];
            sumB += p[tt][2] + p[tt][3];
        }

        // ---- C-frag -> fp16 A-frag: direct pack, NO shuffles ----
        unsigned a0 = pack_f16(p[0][0], p[0][1]);   // row g,   k-cols 2tig,2tig+1
        unsigned a1 = pack_f16(p[0][2], p[0][3]);   // row g+8, k-cols 2tig,2tig+1
        unsigned a2 = pack_f16(p[1][0], p[1][1]);   // row g,   k-cols 2tig+8,+9
        unsigned a3 = pack_f16(p[1][2], p[1][3]);   // row g+8, k-cols 2tig+8,+9

        // ---- AV: one fp16 m16n8k16 mma per nn ----
        #pragma unroll
        for (int nn = 0; nn < 4; nn++) {
            uint2 bb = *(const uint2*)(vfrag + (tp * 4 + nn) * 64 + lane * 2);
            mma_f16(av[nn][0], av[nn][1], av[nn][2], av[nn][3],
                    a0, a1, a2, a3, bb.x, bb.y);
        }

        if (tp < 21) {
            #pragma unroll
            for (int tt = 0; tt < 2; tt++)
                #pragma unroll
                for (int e = 0; e < 4; e++) cbq[tt][e] = cbn[tt][e];
        }
    }

    sumA += __shfl_xor_sync(0xffffffffu, sumA, 1);
    sumA += __shfl_xor_sync(0xffffffffu, sumA, 2);
    sumB += __shfl_xor_sync(0xffffffffu, sumB, 1);
    sumB += __shfl_xor_sync(0xffffffffu, sumB, 2);
    const float invA = 1.0f / sumA;
    const float invB = 1.0f / sumB;

    #pragma unroll
    for (int nn = 0; nn < 4; nn++) {
        const int d = nn * 8 + 2 * tig;
        if (vA) {
            float2 o = make_float2(av[nn][0] * invA, av[nn][1] * invA);
            *(float2*)(g_ao + ((size_t)b * N_TOK + iA) * DIM + h * HD + d) = o;
        }
        if (vB) {
            float2 o = make_float2(av[nn][2] * invB, av[nn][3] * invB);
            *(float2*)(g_ao + ((size_t)b * N_TOK + iB) * DIM + h * HD + d) = o;
        }
    }
}

// ---------------- kernel 2: output projection ------------------------------
__global__ __launch_bounds__(256, 2)
void proj_kernel(const float* __restrict__ w,
                 const float* __restrict__ bias,
                 float* __restrict__ out) {
    extern __shared__ float smf[];
    unsigned* xs    = (unsigned*)smf;            // [128][100] tf32 bits
    unsigned* wfrag = (unsigned*)smf + 12800;    // [144][64]
    float*    bs    = smf + 12800 + 9216;        // [96]
    const int tid = threadIdx.x;
    const int m0  = blockIdx.x * 128;

    for (int idx = tid; idx < 12 * 12 * 32; idx += 256) {
        int t = idx >> 5, l = idx & 31;
        int nt = t / 12, kk = t - nt * 12;
        int gl = l >> 2, tl = l & 3;
        int c  = nt * 8 + gl;
        int k0 = kk * 8 + tl;
        wfrag[t * 64 + l * 2]     = f2tf(w[c * 96 + k0]);
        wfrag[t * 64 + l * 2 + 1] = f2tf(w[c * 96 + k0 + 4]);
    }
    if (tid < 96) bs[tid] = bias[tid];
    for (int idx = tid; idx < 128 * 96; idx += 256) {
        int r = idx / 96, c = idx - r * 96;
        xs[r * 100 + c] = f2tf(g_ao[(size_t)m0 * 96 + idx]);
    }
    __syncthreads();

    const int wp   = tid >> 5;
    const int lane = tid & 31;
    const int g    = lane >> 2;
    const int tig  = lane & 3;
    const int cg   = wp & 3;
    const int mh   = wp >> 2;

    uint2 breg[12][3];
    #pragma unroll
    for (int kk = 0; kk < 12; kk++)
        #pragma unroll
        for (int ntl = 0; ntl < 3; ntl++)
            breg[kk][ntl] = *(const uint2*)(wfrag + ((3 * cg + ntl) * 12 + kk) * 64 + lane * 2);

    #pragma unroll
    for (int s = 0; s < 4; s++) {
        const unsigned* xrA = xs + (mh * 64 + s * 16 + g) * 100;
        const unsigned* xrB = xrA + 800;

        float acc[3][4];
        #pragma unroll
        for (int ntl = 0; ntl < 3; ntl++)
            #pragma unroll
            for (int e = 0; e < 4; e++) acc[ntl][e] = 0.f;

        #pragma unroll
        for (int kk = 0; kk < 12; kk++) {
            unsigned a0 = xrA[kk * 8 + tig];
            unsigned a1 = xrB[kk * 8 + tig];
            unsigned a2 = xrA[kk * 8 + tig + 4];
            unsigned a3 = xrB[kk * 8 + tig + 4];
            #pragma unroll
            for (int ntl = 0; ntl < 3; ntl++)
                mma_tf32(acc[ntl][0], acc[ntl][1], acc[ntl][2], acc[ntl][3],
                         a0, a1, a2, a3, breg[kk][ntl].x, breg[kk][ntl].y);
        }

        const size_t mA = m0 + mh * 64 + s * 16 + g;
        const size_t mB = mA + 8;
        #pragma unroll
        for (int ntl = 0; ntl < 3; ntl++) {
            int c0 = (3 * cg + ntl) * 8 + 2 * tig;
            float bb0 = bs[c0], bb1 = bs[c0 + 1];
            *(float2*)(out + mA * 96 + c0) = make_float2(acc[ntl][0] + bb0, acc[ntl][1] + bb1);
            *(float2*)(out + mB * 96 + c0) = make_float2(acc[ntl][2] + bb0, acc[ntl][3] + bb1);
        }
    }
}

// ---------------- launch ---------------------------------------------------
extern "C" void kernel_launch(void* const* d_in, const int* in_sizes, int n_in,
                              void* d_out, int out_size) {
    const float* x      = (const float*)d_in[0];
    const float* mask   = (const float*)d_in[1];
    const float* qkv_w  = (const float*)d_in[2];
    const float* qkv_b  = (const float*)d_in[3];
    const float* proj_w = (const float*)d_in[4];
    const float* proj_b = (const float*)d_in[5];
    const float* rpb    = (const float*)d_in[6];
    const int*   relidx = (const int*)d_in[7];
    float* out = (float*)d_out;

    const int smem_attn = (11264 + 5632 + 9216 + 12800 + 288) * 4;  // 156,800 B
    const int smem_proj = (12800 + 9216 + 96) * 4;                  //  88,448 B
    cudaFuncSetAttribute(attn_kernel, cudaFuncAttributeMaxDynamicSharedMemorySize, smem_attn);
    cudaFuncSetAttribute(proj_kernel, cudaFuncAttributeMaxDynamicSharedMemorySize, smem_proj);

    cb_kernel  <<<dim3(N_TOK, NW * HEADS), 352>>>(mask, rpb, relidx);
    attn_kernel<<<B_TOT * HEADS, 704, smem_attn>>>(x, qkv_w, qkv_b);
    proj_kernel<<<1372, 256, smem_proj>>>(proj_w, proj_b, out);
    (void)in_sizes; (void)n_in; (void)out_size;
}

// round 12
// speedup vs baseline: 1.3272x; 1.0820x over previous
#include <cuda_runtime.h>
#include <cuda_fp16.h>
#include <math.h>

#define B_TOT 512
#define N_TOK 343
#define DIM   96
#define HEADS 3
#define HD    32
#define NW    64
#define CB_STRIDE 344
#define CB_SLICE  (N_TOK * CB_STRIDE)   // 117992
#define TABLE_LEN 2197

// ---------------- scratch (device globals: no allocation allowed) ----------
__device__ float g_ao[(size_t)B_TOT * N_TOK * DIM];          // [B][N][H*hd]
__device__ float g_cb[(size_t)NW * HEADS * CB_SLICE + 64];   // (mask+bias)*log2e

// ---------------- helpers --------------------------------------------------
__device__ __forceinline__ float ex2f(float x) {
    float r;
    asm("ex2.approx.f32 %0, %1;" : "=f"(r) : "f"(x));
    return r;
}

__device__ __forceinline__ unsigned f2tf(float x) {
    unsigned r;
    asm("cvt.rna.tf32.f32 %0, %1;" : "=r"(r) : "f"(x));
    return r;
}

// pack two f32 into f16x2: lo -> lower half, hi -> upper half
__device__ __forceinline__ unsigned pack_f16(float lo, float hi) {
    unsigned d;
    asm("cvt.rn.f16x2.f32 %0, %1, %2;" : "=r"(d) : "f"(hi), "f"(lo));
    return d;
}

__device__ __forceinline__ void mma_tf32(float& c0, float& c1, float& c2, float& c3,
                                         unsigned a0, unsigned a1, unsigned a2, unsigned a3,
                                         unsigned b0, unsigned b1) {
    asm volatile("mma.sync.aligned.m16n8k8.row.col.f32.tf32.tf32.f32 "
                 "{%0,%1,%2,%3}, {%4,%5,%6,%7}, {%8,%9}, {%0,%1,%2,%3};"
                 : "+f"(c0), "+f"(c1), "+f"(c2), "+f"(c3)
                 : "r"(a0), "r"(a1), "r"(a2), "r"(a3), "r"(b0), "r"(b1));
}

__device__ __forceinline__ void mma_f16(float& c0, float& c1, float& c2, float& c3,
                                        unsigned a0, unsigned a1, unsigned a2, unsigned a3,
                                        unsigned b0, unsigned b1) {
    asm volatile("mma.sync.aligned.m16n8k16.row.col.f32.f16.f16.f32 "
                 "{%0,%1,%2,%3}, {%4,%5,%6,%7}, {%8,%9}, {%0,%1,%2,%3};"
                 : "+f"(c0), "+f"(c1), "+f"(c2), "+f"(c3)
                 : "r"(a0), "r"(a1), "r"(a2), "r"(a3), "r"(b0), "r"(b1));
}

// vfrag HALF index for V value at (row j, col d)  (fp16 m16n8k16 B layout)
__device__ __forceinline__ int vhpos(int j, int d) {
    return (((j >> 4) * 4 + (d >> 3)) << 7)
         + (((d & 7) * 4 + ((j >> 1) & 3)) << 2) + (((j >> 3) & 1) << 1) + (j & 1);
}

// ---------------- kernel 0: combined bias table, rpb staged in smem --------
__global__ __launch_bounds__(352)
void cb_kernel(const float* __restrict__ mask,
               const float* __restrict__ rpb,
               const int*   __restrict__ relidx) {
    __shared__ float rpbs[TABLE_LEN];
    const int wh    = blockIdx.x;
    const int chunk = blockIdx.y;
    const int w     = wh / HEADS;
    const int h     = wh - w * HEADS;
    const int tid   = threadIdx.x;
    for (int t = tid; t < TABLE_LEN; t += 352)
        rpbs[t] = rpb[t * HEADS + h] * 1.4426950408889634f;
    __syncthreads();
    const int i0 = chunk * 86;
    const int i1 = (i0 + 86 < N_TOK) ? i0 + 86 : N_TOK;
    if (tid < N_TOK) {
        for (int i = i0; i < i1; i++) {
            int rel = relidx[i * N_TOK + tid];
            g_cb[(size_t)wh * CB_SLICE + i * CB_STRIDE + tid] =
                fmaf(mask[(size_t)w * N_TOK * N_TOK + i * N_TOK + tid],
                     1.4426950408889634f, rpbs[rel]);
        }
    }
}

// ---------------- kernel 1: FUSED qkv + attention --------------------------
// One CTA = (window, head). K and V live as fp16 m16n8k16 B-fragments; Q as
// fp16 A-fragments (direct C-frag pack, no shuffles). Mainloop per tile-pair:
// 4 fp16 QK mma -> ex2 -> pack -> 4 fp16 AV mma. All accumulation f32.
__global__ __launch_bounds__(704, 1)
void attn_kernel(const float* __restrict__ xg,
                 const float* __restrict__ qkvw,
                 const float* __restrict__ qkvb) {
    extern __shared__ unsigned smu[];
    unsigned* kfrag = smu;               // [44*2][64] f16x2       :  5632 words
    unsigned* vfrag = smu + 5632;        // [22*4][64] f16x2       :  5632 words
    unsigned* wf    = smu + 11264;       // [3][4][12][64] tf32    :  9216 words
    unsigned* xs    = smu + 20480;       // [128][100] tf32 bits   : 12800 words
    float*    bsm   = (float*)(smu + 33280);   // [288]
    __half*   vh    = (__half*)vfrag;

    const int bid  = blockIdx.x;
    const int wh   = bid >> 3;                 // window*3 + h
    const int rep  = bid & 7;
    const int win  = wh / HEADS;
    const int h    = wh - win * HEADS;
    const int b    = rep * NW + win;
    const int tid  = threadIdx.x;
    const int lane = tid & 31;
    const int w    = tid >> 5;           // 0..21
    const int g    = lane >> 2;          // 0..7
    const int tig  = lane & 3;           // 0..3

    const float* xrow0 = xg + (size_t)b * N_TOK * DIM;
    const float* cbp   = g_cb + (size_t)wh * CB_SLICE;
    const float qscale = 0.17677669529663687f * 1.4426950408889634f;  // /sqrt(32) * log2e

    // ---- stage weight B-fragments for this head ----
    for (int idx = tid; idx < 3 * 4 * 12 * 32; idx += 704) {
        int t = idx >> 5, l = idx & 31;
        int third = t / 48, rem = t - third * 48;
        int nt = rem / 12, kk = rem - nt * 12;
        int gl = l >> 2, tl = l & 3;
        int c  = third * 96 + h * 32 + nt * 8 + gl;
        int k0 = kk * 8 + tl;
        wf[t * 64 + l * 2]     = f2tf(qkvw[c * 96 + k0]);
        wf[t * 64 + l * 2 + 1] = f2tf(qkvw[c * 96 + k0 + 4]);
    }
    for (int idx = tid; idx < 96; idx += 704) {
        bsm[idx] = qkvb[idx + h * 32 + ((idx >> 5) * 64)];  // bsm[third*32+cc] = qkvb[third*96+h*32+cc]
    }

    unsigned qa[2][4];   // fp16 Q A-fragments, 2 k16 chunks

    // ---- chunks of 128 rows: compute K,V into frags; Q for owning warps ----
    #pragma unroll 1
    for (int c = 0; c < 3; c++) {
        if (c > 0) __syncthreads();
        for (int idx = tid; idx < 128 * 96; idx += 704) {
            int r = idx / 96, cc = idx - r * 96;
            int n = 128 * c + r;
            float v = (n < N_TOK) ? xrow0[(size_t)n * 96 + cc] : 0.f;
            xs[r * 100 + cc] = f2tf(v);
        }
        __syncthreads();

        // K/V units: u = (s<<2) | (third01<<1) | nhalf, 32 units over 22 warps
        for (int u = w; u < 32; u += 22) {
            int s = u >> 2, th = (u >> 1) & 1, nh = u & 1;
            const unsigned* xrA = xs + (s * 16 + g) * 100;
            const unsigned* xrB = xrA + 800;
            #pragma unroll
            for (int ntl = 0; ntl < 2; ntl++) {
                int nt = nh * 2 + ntl;
                float a0f = 0.f, a1f = 0.f, a2f = 0.f, a3f = 0.f;
                #pragma unroll
                for (int kk = 0; kk < 12; kk++) {
                    unsigned a0 = xrA[kk * 8 + tig];
                    unsigned a1 = xrB[kk * 8 + tig];
                    unsigned a2 = xrA[kk * 8 + tig + 4];
                    unsigned a3 = xrB[kk * 8 + tig + 4];
                    uint2 bb = *(const uint2*)(wf + (((th + 1) * 48) + nt * 12 + kk) * 64 + lane * 2);
                    mma_tf32(a0f, a1f, a2f, a3f, a0, a1, a2, a3, bb.x, bb.y);
                }
                int c0 = nt * 8 + 2 * tig;
                float b0 = bsm[(th + 1) * 32 + c0];
                float b1 = bsm[(th + 1) * 32 + c0 + 1];
                int nA = 128 * c + s * 16 + g;
                int nB = nA + 8;
                float v00 = a0f + b0, v01 = a1f + b1;    // row nA
                float v10 = a2f + b0, v11 = a3f + b1;    // row nB
                if (th == 0) {
                    // K fp16 B-frag: word = tile(ntok, d-chunk)*64 + lane*2 + (nt&1)
                    int tcol = nt >> 1, reg = nt & 1;
                    if (nA < 352)
                        kfrag[((((nA >> 3) << 1) + tcol) << 6) + (lane << 1) + reg] = pack_f16(v00, v01);
                    if (nB < 352)
                        kfrag[((((nB >> 3) << 1) + tcol) << 6) + (lane << 1) + reg] = pack_f16(v10, v11);
                } else {
                    if (nA < 352) {
                        vh[vhpos(nA, c0)]     = __float2half_rn(v00);
                        vh[vhpos(nA, c0 + 1)] = __float2half_rn(v01);
                    }
                    if (nB < 352) {
                        vh[vhpos(nB, c0)]     = __float2half_rn(v10);
                        vh[vhpos(nB, c0 + 1)] = __float2half_rn(v11);
                    }
                }
            }
        }

        // Q for warps whose stripe lives in this chunk: direct fp16 pack
        if ((w >> 3) == c) {
            const int s = w & 7;
            const unsigned* xrA = xs + (s * 16 + g) * 100;
            const unsigned* xrB = xrA + 800;
            #pragma unroll
            for (int nt = 0; nt < 4; nt++) {
                float a0f = 0.f, a1f = 0.f, a2f = 0.f, a3f = 0.f;
                #pragma unroll
                for (int kk = 0; kk < 12; kk++) {
                    unsigned a0 = xrA[kk * 8 + tig];
                    unsigned a1 = xrB[kk * 8 + tig];
                    unsigned a2 = xrA[kk * 8 + tig + 4];
                    unsigned a3 = xrB[kk * 8 + tig + 4];
                    uint2 bb = *(const uint2*)(wf + (nt * 12 + kk) * 64 + lane * 2);
                    mma_tf32(a0f, a1f, a2f, a3f, a0, a1, a2, a3, bb.x, bb.y);
                }
                int c0 = nt * 8 + 2 * tig;
                float b0 = bsm[c0], b1 = bsm[c0 + 1];
                qa[nt >> 1][(nt & 1) * 2 + 0] = pack_f16((a0f + b0) * qscale, (a1f + b1) * qscale);
                qa[nt >> 1][(nt & 1) * 2 + 1] = pack_f16((a2f + b0) * qscale, (a3f + b1) * qscale);
            }
        }
    }
    __syncthreads();

    // ---- mainloop ----
    const int i0 = w * 16;
    const int iA = i0 + g, iB = i0 + g + 8;
    const bool vA = (iA < N_TOK), vB = (iB < N_TOK);

    float av[4][4];
    #pragma unroll
    for (int nn = 0; nn < 4; nn++)
        #pragma unroll
        for (int e = 0; e < 4; e++) av[nn][e] = 0.f;

    float sumA = 0.f, sumB = 0.f;
    const float* cbA = cbp + (size_t)iA * CB_STRIDE;
    const float* cbB = cbp + (size_t)iB * CB_STRIDE;

    // cb double buffer: load pair 0 before the loop
    float cbq[2][4];
    #pragma unroll
    for (int tt = 0; tt < 2; tt++) {
        const int j0 = tt * 8 + 2 * tig;
        float c00, c01, c10, c11;
        if (vA) { float2 t = *(const float2*)(cbA + j0); c00 = t.x; c01 = t.y; }
        else    { c00 = c01 = -1e30f; }
        if (vB) { float2 t = *(const float2*)(cbB + j0); c10 = t.x; c11 = t.y; }
        else    { c10 = c11 = -1e30f; }
        cbq[tt][0] = c00; cbq[tt][1] = c01; cbq[tt][2] = c10; cbq[tt][3] = c11;
    }

    #pragma unroll 1
    for (int tp = 0; tp < 22; tp++) {
        // ---- prefetch cb for next tile pair ----
        float cbn[2][4];
        if (tp < 21) {
            #pragma unroll
            for (int tt = 0; tt < 2; tt++) {
                const int j0 = (2 * (tp + 1) + tt) * 8 + 2 * tig;
                float c00, c01, c10, c11;
                if (vA && j0 < N_TOK) { float2 t = *(const float2*)(cbA + j0); c00 = t.x; c01 = t.y; }
                else                  { c00 = c01 = -1e30f; }
                if (vB && j0 < N_TOK) { float2 t = *(const float2*)(cbB + j0); c10 = t.x; c11 = t.y; }
                else                  { c10 = c11 = -1e30f; }
                if (j0 + 1 >= N_TOK)  { c01 = -1e30f; c11 = -1e30f; }
                cbn[tt][0] = c00; cbn[tt][1] = c01; cbn[tt][2] = c10; cbn[tt][3] = c11;
            }
        }

        // ---- QK: 2 fp16 m16n8k16 mma per n8-tile ----
        float c[2][4];
        #pragma unroll
        for (int tt = 0; tt < 2; tt++) {
            c[tt][0] = c[tt][1] = c[tt][2] = c[tt][3] = 0.f;
            const int ntg = 2 * tp + tt;
            uint2 bk0 = *(const uint2*)(kfrag + (ntg * 2 + 0) * 64 + lane * 2);
            uint2 bk1 = *(const uint2*)(kfrag + (ntg * 2 + 1) * 64 + lane * 2);
            mma_f16(c[tt][0], c[tt][1], c[tt][2], c[tt][3],
                    qa[0][0], qa[0][1], qa[0][2], qa[0][3], bk0.x, bk0.y);
            mma_f16(c[tt][0], c[tt][1], c[tt][2], c[tt][3],
                    qa[1][0], qa[1][1], qa[1][2], qa[1][3], bk1.x, bk1.y);
        }

        // ---- exp via ex2.approx (log2-domain scores) ----
        float p[2][4];
        #pragma unroll
        for (int tt = 0; tt < 2; tt++) {
            p[tt][0] = ex2f(c[tt][0] + cbq[tt][0]);
            p[tt][1] = ex2f(c[tt][1] + cbq[tt][1]);
            p[tt][2] = ex2f(c[tt][2] + cbq[tt][2]);
            p[tt][3] = ex2f(c[tt][3] + cbq[tt][3]);
            sumA += p[tt][0] + p[tt][1];
            sumB += p[tt][2] + p[tt][3];
        }

        // ---- C-frag -> fp16 A-frag: direct pack, NO shuffles ----
        unsigned a0 = pack_f16(p[0][0], p[0][1]);
        unsigned a1 = pack_f16(p[0][2], p[0][3]);
        unsigned a2 = pack_f16(p[1][0], p[1][1]);
        unsigned a3 = pack_f16(p[1][2], p[1][3]);

        // ---- AV: one fp16 m16n8k16 mma per nn ----
        #pragma unroll
        for (int nn = 0; nn < 4; nn++) {
            uint2 bb = *(const uint2*)(vfrag + (tp * 4 + nn) * 64 + lane * 2);
            mma_f16(av[nn][0], av[nn][1], av[nn][2], av[nn][3],
                    a0, a1, a2, a3, bb.x, bb.y);
        }

        if (tp < 21) {
            #pragma unroll
            for (int tt = 0; tt < 2; tt++)
                #pragma unroll
                for (int e = 0; e < 4; e++) cbq[tt][e] = cbn[tt][e];
        }
    }

    sumA += __shfl_xor_sync(0xffffffffu, sumA, 1);
    sumA += __shfl_xor_sync(0xffffffffu, sumA, 2);
    sumB += __shfl_xor_sync(0xffffffffu, sumB, 1);
    sumB += __shfl_xor_sync(0xffffffffu, sumB, 2);
    const float invA = 1.0f / sumA;
    const float invB = 1.0f / sumB;

    #pragma unroll
    for (int nn = 0; nn < 4; nn++) {
        const int d = nn * 8 + 2 * tig;
        if (vA) {
            float2 o = make_float2(av[nn][0] * invA, av[nn][1] * invA);
            *(float2*)(g_ao + ((size_t)b * N_TOK + iA) * DIM + h * HD + d) = o;
        }
        if (vB) {
            float2 o = make_float2(av[nn][2] * invB, av[nn][3] * invB);
            *(float2*)(g_ao + ((size_t)b * N_TOK + iB) * DIM + h * HD + d) = o;
        }
    }
}

// ---------------- kernel 2: output projection ------------------------------
__global__ __launch_bounds__(256, 2)
void proj_kernel(const float* __restrict__ w,
                 const float* __restrict__ bias,
                 float* __restrict__ out) {
    extern __shared__ float smf[];
    unsigned* xs    = (unsigned*)smf;            // [128][100] tf32 bits
    unsigned* wfrag = (unsigned*)smf + 12800;    // [144][64]
    float*    bs    = smf + 12800 + 9216;        // [96]
    const int tid = threadIdx.x;
    const int m0  = blockIdx.x * 128;

    for (int idx = tid; idx < 12 * 12 * 32; idx += 256) {
        int t = idx >> 5, l = idx & 31;
        int nt = t / 12, kk = t - nt * 12;
        int gl = l >> 2, tl = l & 3;
        int c  = nt * 8 + gl;
        int k0 = kk * 8 + tl;
        wfrag[t * 64 + l * 2]     = f2tf(w[c * 96 + k0]);
        wfrag[t * 64 + l * 2 + 1] = f2tf(w[c * 96 + k0 + 4]);
    }
    if (tid < 96) bs[tid] = bias[tid];
    for (int idx = tid; idx < 128 * 96; idx += 256) {
        int r = idx / 96, c = idx - r * 96;
        xs[r * 100 + c] = f2tf(g_ao[(size_t)m0 * 96 + idx]);
    }
    __syncthreads();

    const int wp   = tid >> 5;
    const int lane = tid & 31;
    const int g    = lane >> 2;
    const int tig  = lane & 3;
    const int cg   = wp & 3;
    const int mh   = wp >> 2;

    uint2 breg[12][3];
    #pragma unroll
    for (int kk = 0; kk < 12; kk++)
        #pragma unroll
        for (int ntl = 0; ntl < 3; ntl++)
            breg[kk][ntl] = *(const uint2*)(wfrag + ((3 * cg + ntl) * 12 + kk) * 64 + lane * 2);

    #pragma unroll
    for (int s = 0; s < 4; s++) {
        const unsigned* xrA = xs + (mh * 64 + s * 16 + g) * 100;
        const unsigned* xrB = xrA + 800;

        float acc[3][4];
        #pragma unroll
        for (int ntl = 0; ntl < 3; ntl++)
            #pragma unroll
            for (int e = 0; e < 4; e++) acc[ntl][e] = 0.f;

        #pragma unroll
        for (int kk = 0; kk < 12; kk++) {
            unsigned a0 = xrA[kk * 8 + tig];
            unsigned a1 = xrB[kk * 8 + tig];
            unsigned a2 = xrA[kk * 8 + tig + 4];
            unsigned a3 = xrB[kk * 8 + tig + 4];
            #pragma unroll
            for (int ntl = 0; ntl < 3; ntl++)
                mma_tf32(acc[ntl][0], acc[ntl][1], acc[ntl][2], acc[ntl][3],
                         a0, a1, a2, a3, breg[kk][ntl].x, breg[kk][ntl].y);
        }

        const size_t mA = m0 + mh * 64 + s * 16 + g;
        const size_t mB = mA + 8;
        #pragma unroll
        for (int ntl = 0; ntl < 3; ntl++) {
            int c0 = (3 * cg + ntl) * 8 + 2 * tig;
            float bb0 = bs[c0], bb1 = bs[c0 + 1];
            *(float2*)(out + mA * 96 + c0) = make_float2(acc[ntl][0] + bb0, acc[ntl][1] + bb1);
            *(float2*)(out + mB * 96 + c0) = make_float2(acc[ntl][2] + bb0, acc[ntl][3] + bb1);
        }
    }
}

// ---------------- launch ---------------------------------------------------
extern "C" void kernel_launch(void* const* d_in, const int* in_sizes, int n_in,
                              void* d_out, int out_size) {
    const float* x      = (const float*)d_in[0];
    const float* mask   = (const float*)d_in[1];
    const float* qkv_w  = (const float*)d_in[2];
    const float* qkv_b  = (const float*)d_in[3];
    const float* proj_w = (const float*)d_in[4];
    const float* proj_b = (const float*)d_in[5];
    const float* rpb    = (const float*)d_in[6];
    const int*   relidx = (const int*)d_in[7];
    float* out = (float*)d_out;

    const int smem_attn = (5632 + 5632 + 9216 + 12800 + 288) * 4;  // 134,272 B
    const int smem_proj = (12800 + 9216 + 96) * 4;                 //  88,448 B
    cudaFuncSetAttribute(attn_kernel, cudaFuncAttributeMaxDynamicSharedMemorySize, smem_attn);
    cudaFuncSetAttribute(proj_kernel, cudaFuncAttributeMaxDynamicSharedMemorySize, smem_proj);

    cb_kernel  <<<dim3(NW * HEADS, 4), 352>>>(mask, rpb, relidx);
    attn_kernel<<<B_TOT * HEADS, 704, smem_attn>>>(x, qkv_w, qkv_b);
    proj_kernel<<<1372, 256, smem_proj>>>(proj_w, proj_b, out);
    (void)in_sizes; (void)n_in; (void)out_size;
}

// round 13
// speedup vs baseline: 1.4075x; 1.0605x over previous
#include <cuda_runtime.h>
#include <cuda_fp16.h>
#include <math.h>

#define B_TOT 512
#define N_TOK 343
#define DIM   96
#define HEADS 3
#define HD    32
#define NW    64
#define CB_STRIDE 344
#define CB_SLICE  (N_TOK * CB_STRIDE)   // 117992
#define TABLE_LEN 2197
#define ONES_F16X2 0x3C003C00u

// ---------------- scratch (device globals: no allocation allowed) ----------
__device__ __half g_ao[(size_t)B_TOT * N_TOK * DIM];         // [B][N][H*hd] fp16
__device__ float  g_cb[(size_t)NW * HEADS * CB_SLICE + 64];  // (mask+bias)*log2e

// ---------------- helpers --------------------------------------------------
__device__ __forceinline__ unsigned ex2_f16x2(unsigned x) {
    unsigned r;
    asm("ex2.approx.f16x2 %0, %1;" : "=r"(r) : "r"(x));
    return r;
}

__device__ __forceinline__ unsigned f2tf(float x) {
    unsigned r;
    asm("cvt.rna.tf32.f32 %0, %1;" : "=r"(r) : "f"(x));
    return r;
}

// pack two f32 into f16x2: lo -> lower half, hi -> upper half
__device__ __forceinline__ unsigned pack_f16(float lo, float hi) {
    unsigned d;
    asm("cvt.rn.f16x2.f32 %0, %1, %2;" : "=r"(d) : "f"(hi), "f"(lo));
    return d;
}

__device__ __forceinline__ void mma_tf32(float& c0, float& c1, float& c2, float& c3,
                                         unsigned a0, unsigned a1, unsigned a2, unsigned a3,
                                         unsigned b0, unsigned b1) {
    asm volatile("mma.sync.aligned.m16n8k8.row.col.f32.tf32.tf32.f32 "
                 "{%0,%1,%2,%3}, {%4,%5,%6,%7}, {%8,%9}, {%0,%1,%2,%3};"
                 : "+f"(c0), "+f"(c1), "+f"(c2), "+f"(c3)
                 : "r"(a0), "r"(a1), "r"(a2), "r"(a3), "r"(b0), "r"(b1));
}

__device__ __forceinline__ void mma_f16(float& c0, float& c1, float& c2, float& c3,
                                        unsigned a0, unsigned a1, unsigned a2, unsigned a3,
                                        unsigned b0, unsigned b1) {
    asm volatile("mma.sync.aligned.m16n8k16.row.col.f32.f16.f16.f32 "
                 "{%0,%1,%2,%3}, {%4,%5,%6,%7}, {%8,%9}, {%0,%1,%2,%3};"
                 : "+f"(c0), "+f"(c1), "+f"(c2), "+f"(c3)
                 : "r"(a0), "r"(a1), "r"(a2), "r"(a3), "r"(b0), "r"(b1));
}

// vfrag HALF index for V value at (row j, col d)  (fp16 m16n8k16 B layout)
__device__ __forceinline__ int vhpos(int j, int d) {
    return (((j >> 4) * 4 + (d >> 3)) << 7)
         + (((d & 7) * 4 + ((j >> 1) & 3)) << 2) + (((j >> 3) & 1) << 1) + (j & 1);
}

// ---------------- kernel 0: combined bias table, rpb staged in smem --------
__global__ __launch_bounds__(352)
void cb_kernel(const float* __restrict__ mask,
               const float* __restrict__ rpb,
               const int*   __restrict__ relidx) {
    __shared__ float rpbs[TABLE_LEN];
    const int wh    = blockIdx.x;
    const int chunk = blockIdx.y;
    const int w     = wh / HEADS;
    const int h     = wh - w * HEADS;
    const int tid   = threadIdx.x;
    for (int t = tid; t < TABLE_LEN; t += 352)
        rpbs[t] = rpb[t * HEADS + h] * 1.4426950408889634f;
    __syncthreads();
    const int i0 = chunk * 86;
    const int i1 = (i0 + 86 < N_TOK) ? i0 + 86 : N_TOK;
    if (tid < N_TOK) {
        for (int i = i0; i < i1; i++) {
            int rel = relidx[i * N_TOK + tid];
            g_cb[(size_t)wh * CB_SLICE + i * CB_STRIDE + tid] =
                fmaf(mask[(size_t)w * N_TOK * N_TOK + i * N_TOK + tid],
                     1.4426950408889634f, rpbs[rel]);
        }
    }
}

// ---------------- kernel 1: FUSED qkv + attention --------------------------
// One CTA = (window, head). K/V as fp16 m16n8k16 B-fragments, Q as fp16
// A-fragments. Mainloop per tile-pair: 4 fp16 QK mma -> f32 bias add ->
// pack -> ex2.f16x2 (output IS the A-frag) -> 4 AV mma + 1 ones-column mma
// (tensor-core rowsum; no shuffles, no scalar sum chain).
__global__ __launch_bounds__(704, 1)
void attn_kernel(const float* __restrict__ xg,
                 const float* __restrict__ qkvw,
                 const float* __restrict__ qkvb) {
    extern __shared__ unsigned smu[];
    unsigned* kfrag = smu;               // [44*2][64] f16x2       :  5632 words
    unsigned* vfrag = smu + 5632;        // [22*4][64] f16x2       :  5632 words
    unsigned* wf    = smu + 11264;       // [3][4][12][64] tf32    :  9216 words
    unsigned* xs    = smu + 20480;       // [128][100] tf32 bits   : 12800 words
    float*    bsm   = (float*)(smu + 33280);   // [288]
    __half*   vh    = (__half*)vfrag;

    const int bid  = blockIdx.x;
    const int wh   = bid >> 3;                 // window*3 + h
    const int rep  = bid & 7;
    const int win  = wh / HEADS;
    const int h    = wh - win * HEADS;
    const int b    = rep * NW + win;
    const int tid  = threadIdx.x;
    const int lane = tid & 31;
    const int w    = tid >> 5;           // 0..21
    const int g    = lane >> 2;          // 0..7
    const int tig  = lane & 3;           // 0..3

    const float* xrow0 = xg + (size_t)b * N_TOK * DIM;
    const float* cbp   = g_cb + (size_t)wh * CB_SLICE;
    const float qscale = 0.17677669529663687f * 1.4426950408889634f;  // /sqrt(32) * log2e

    // ---- stage weight B-fragments for this head ----
    for (int idx = tid; idx < 3 * 4 * 12 * 32; idx += 704) {
        int t = idx >> 5, l = idx & 31;
        int third = t / 48, rem = t - third * 48;
        int nt = rem / 12, kk = rem - nt * 12;
        int gl = l >> 2, tl = l & 3;
        int c  = third * 96 + h * 32 + nt * 8 + gl;
        int k0 = kk * 8 + tl;
        wf[t * 64 + l * 2]     = f2tf(qkvw[c * 96 + k0]);
        wf[t * 64 + l * 2 + 1] = f2tf(qkvw[c * 96 + k0 + 4]);
    }
    for (int idx = tid; idx < 96; idx += 704) {
        bsm[idx] = qkvb[idx + h * 32 + ((idx >> 5) * 64)];  // bsm[third*32+cc] = qkvb[third*96+h*32+cc]
    }

    unsigned qa[2][4];   // fp16 Q A-fragments, 2 k16 chunks

    // ---- chunks of 128 rows: compute K,V into frags; Q for owning warps ----
    #pragma unroll 1
    for (int c = 0; c < 3; c++) {
        if (c > 0) __syncthreads();
        for (int idx = tid; idx < 128 * 96; idx += 704) {
            int r = idx / 96, cc = idx - r * 96;
            int n = 128 * c + r;
            float v = (n < N_TOK) ? xrow0[(size_t)n * 96 + cc] : 0.f;
            xs[r * 100 + cc] = f2tf(v);
        }
        __syncthreads();

        // K/V units: u = (s<<2) | (third01<<1) | nhalf, 32 units over 22 warps
        for (int u = w; u < 32; u += 22) {
            int s = u >> 2, th = (u >> 1) & 1, nh = u & 1;
            const unsigned* xrA = xs + (s * 16 + g) * 100;
            const unsigned* xrB = xrA + 800;
            #pragma unroll
            for (int ntl = 0; ntl < 2; ntl++) {
                int nt = nh * 2 + ntl;
                float a0f = 0.f, a1f = 0.f, a2f = 0.f, a3f = 0.f;
                #pragma unroll
                for (int kk = 0; kk < 12; kk++) {
                    unsigned a0 = xrA[kk * 8 + tig];
                    unsigned a1 = xrB[kk * 8 + tig];
                    unsigned a2 = xrA[kk * 8 + tig + 4];
                    unsigned a3 = xrB[kk * 8 + tig + 4];
                    uint2 bb = *(const uint2*)(wf + (((th + 1) * 48) + nt * 12 + kk) * 64 + lane * 2);
                    mma_tf32(a0f, a1f, a2f, a3f, a0, a1, a2, a3, bb.x, bb.y);
                }
                int c0 = nt * 8 + 2 * tig;
                float b0 = bsm[(th + 1) * 32 + c0];
                float b1 = bsm[(th + 1) * 32 + c0 + 1];
                int nA = 128 * c + s * 16 + g;
                int nB = nA + 8;
                float v00 = a0f + b0, v01 = a1f + b1;    // row nA
                float v10 = a2f + b0, v11 = a3f + b1;    // row nB
                if (th == 0) {
                    int tcol = nt >> 1, reg = nt & 1;
                    if (nA < 352)
                        kfrag[((((nA >> 3) << 1) + tcol) << 6) + (lane << 1) + reg] = pack_f16(v00, v01);
                    if (nB < 352)
                        kfrag[((((nB >> 3) << 1) + tcol) << 6) + (lane << 1) + reg] = pack_f16(v10, v11);
                } else {
                    if (nA < 352) {
                        vh[vhpos(nA, c0)]     = __float2half_rn(v00);
                        vh[vhpos(nA, c0 + 1)] = __float2half_rn(v01);
                    }
                    if (nB < 352) {
                        vh[vhpos(nB, c0)]     = __float2half_rn(v10);
                        vh[vhpos(nB, c0 + 1)] = __float2half_rn(v11);
                    }
                }
            }
        }

        // Q for warps whose stripe lives in this chunk: direct fp16 pack
        if ((w >> 3) == c) {
            const int s = w & 7;
            const unsigned* xrA = xs + (s * 16 + g) * 100;
            const unsigned* xrB = xrA + 800;
            #pragma unroll
            for (int nt = 0; nt < 4; nt++) {
                float a0f = 0.f, a1f = 0.f, a2f = 0.f, a3f = 0.f;
                #pragma unroll
                for (int kk = 0; kk < 12; kk++) {
                    unsigned a0 = xrA[kk * 8 + tig];
                    unsigned a1 = xrB[kk * 8 + tig];
                    unsigned a2 = xrA[kk * 8 + tig + 4];
                    unsigned a3 = xrB[kk * 8 + tig + 4];
                    uint2 bb = *(const uint2*)(wf + (nt * 12 + kk) * 64 + lane * 2);
                    mma_tf32(a0f, a1f, a2f, a3f, a0, a1, a2, a3, bb.x, bb.y);
                }
                int c0 = nt * 8 + 2 * tig;
                float b0 = bsm[c0], b1 = bsm[c0 + 1];
                qa[nt >> 1][(nt & 1) * 2 + 0] = pack_f16((a0f + b0) * qscale, (a1f + b1) * qscale);
                qa[nt >> 1][(nt & 1) * 2 + 1] = pack_f16((a2f + b0) * qscale, (a3f + b1) * qscale);
            }
        }
    }
    __syncthreads();

    // ---- mainloop ----
    const int i0 = w * 16;
    const int iA = i0 + g, iB = i0 + g + 8;
    const bool vA = (iA < N_TOK), vB = (iB < N_TOK);

    float av[5][4];   // [0..3]: output n8 tiles; [4]: ones-column rowsums
    #pragma unroll
    for (int nn = 0; nn < 5; nn++)
        #pragma unroll
        for (int e = 0; e < 4; e++) av[nn][e] = 0.f;

    const float* cbA = cbp + (size_t)iA * CB_STRIDE;
    const float* cbB = cbp + (size_t)iB * CB_STRIDE;

    // cb double buffer: load pair 0 before the loop
    float cbq[2][4];
    #pragma unroll
    for (int tt = 0; tt < 2; tt++) {
        const int j0 = tt * 8 + 2 * tig;
        float c00, c01, c10, c11;
        if (vA) { float2 t = *(const float2*)(cbA + j0); c00 = t.x; c01 = t.y; }
        else    { c00 = c01 = -1e30f; }
        if (vB) { float2 t = *(const float2*)(cbB + j0); c10 = t.x; c11 = t.y; }
        else    { c10 = c11 = -1e30f; }
        cbq[tt][0] = c00; cbq[tt][1] = c01; cbq[tt][2] = c10; cbq[tt][3] = c11;
    }

    #pragma unroll 1
    for (int tp = 0; tp < 22; tp++) {
        // ---- prefetch cb for next tile pair ----
        float cbn[2][4];
        if (tp < 21) {
            #pragma unroll
            for (int tt = 0; tt < 2; tt++) {
                const int j0 = (2 * (tp + 1) + tt) * 8 + 2 * tig;
                float c00, c01, c10, c11;
                if (vA && j0 < N_TOK) { float2 t = *(const float2*)(cbA + j0); c00 = t.x; c01 = t.y; }
                else                  { c00 = c01 = -1e30f; }
                if (vB && j0 < N_TOK) { float2 t = *(const float2*)(cbB + j0); c10 = t.x; c11 = t.y; }
                else                  { c10 = c11 = -1e30f; }
                if (j0 + 1 >= N_TOK)  { c01 = -1e30f; c11 = -1e30f; }
                cbn[tt][0] = c00; cbn[tt][1] = c01; cbn[tt][2] = c10; cbn[tt][3] = c11;
            }
        }

        // ---- QK: 2 fp16 m16n8k16 mma per n8-tile ----
        float c[2][4];
        #pragma unroll
        for (int tt = 0; tt < 2; tt++) {
            c[tt][0] = c[tt][1] = c[tt][2] = c[tt][3] = 0.f;
            const int ntg = 2 * tp + tt;
            uint2 bk0 = *(const uint2*)(kfrag + (ntg * 2 + 0) * 64 + lane * 2);
            uint2 bk1 = *(const uint2*)(kfrag + (ntg * 2 + 1) * 64 + lane * 2);
            mma_f16(c[tt][0], c[tt][1], c[tt][2], c[tt][3],
                    qa[0][0], qa[0][1], qa[0][2], qa[0][3], bk0.x, bk0.y);
            mma_f16(c[tt][0], c[tt][1], c[tt][2], c[tt][3],
                    qa[1][0], qa[1][1], qa[1][2], qa[1][3], bk1.x, bk1.y);
        }

        // ---- bias add (f32) -> pack f16x2 -> ex2.f16x2 == A-frag ----
        unsigned a0, a1, a2, a3;
        {
            unsigned s0 = pack_f16(c[0][0] + cbq[0][0], c[0][1] + cbq[0][1]);
            unsigned s1 = pack_f16(c[0][2] + cbq[0][2], c[0][3] + cbq[0][3]);
            unsigned s2 = pack_f16(c[1][0] + cbq[1][0], c[1][1] + cbq[1][1]);
            unsigned s3 = pack_f16(c[1][2] + cbq[1][2], c[1][3] + cbq[1][3]);
            a0 = ex2_f16x2(s0);   // row g,   k-cols 2tig,2tig+1 (tile 0)
            a1 = ex2_f16x2(s1);   // row g+8
            a2 = ex2_f16x2(s2);   // row g,   k-cols +8
            a3 = ex2_f16x2(s3);   // row g+8
        }

        // ---- AV: 4 output mma + 1 ones-column mma (rowsum in f32) ----
        #pragma unroll
        for (int nn = 0; nn < 4; nn++) {
            uint2 bb = *(const uint2*)(vfrag + (tp * 4 + nn) * 64 + lane * 2);
            mma_f16(av[nn][0], av[nn][1], av[nn][2], av[nn][3],
                    a0, a1, a2, a3, bb.x, bb.y);
        }
        mma_f16(av[4][0], av[4][1], av[4][2], av[4][3],
                a0, a1, a2, a3, ONES_F16X2, ONES_F16X2);

        if (tp < 21) {
            #pragma unroll
            for (int tt = 0; tt < 2; tt++)
                #pragma unroll
                for (int e = 0; e < 4; e++) cbq[tt][e] = cbn[tt][e];
        }
    }

    // rowsums are replicated across all n-columns of the ones tile
    const float invA = 1.0f / av[4][0];
    const float invB = 1.0f / av[4][2];

    __half* aoh = g_ao;
    #pragma unroll
    for (int nn = 0; nn < 4; nn++) {
        const int d = nn * 8 + 2 * tig;
        if (vA) {
            unsigned o = pack_f16(av[nn][0] * invA, av[nn][1] * invA);
            *(unsigned*)(aoh + ((size_t)b * N_TOK + iA) * DIM + h * HD + d) = o;
        }
        if (vB) {
            unsigned o = pack_f16(av[nn][2] * invB, av[nn][3] * invB);
            *(unsigned*)(aoh + ((size_t)b * N_TOK + iB) * DIM + h * HD + d) = o;
        }
    }
}

// ---------------- kernel 2: output projection (reads fp16 g_ao) ------------
__global__ __launch_bounds__(256, 2)
void proj_kernel(const float* __restrict__ w,
                 const float* __restrict__ bias,
                 float* __restrict__ out) {
    extern __shared__ float smf[];
    unsigned* xs    = (unsigned*)smf;            // [128][100] tf32 bits
    unsigned* wfrag = (unsigned*)smf + 12800;    // [144][64]
    float*    bs    = smf + 12800 + 9216;        // [96]
    const int tid = threadIdx.x;
    const int m0  = blockIdx.x * 128;

    for (int idx = tid; idx < 12 * 12 * 32; idx += 256) {
        int t = idx >> 5, l = idx & 31;
        int nt = t / 12, kk = t - nt * 12;
        int gl = l >> 2, tl = l & 3;
        int c  = nt * 8 + gl;
        int k0 = kk * 8 + tl;
        wfrag[t * 64 + l * 2]     = f2tf(w[c * 96 + k0]);
        wfrag[t * 64 + l * 2 + 1] = f2tf(w[c * 96 + k0 + 4]);
    }
    if (tid < 96) bs[tid] = bias[tid];
    {
        const __half2* src = (const __half2*)(g_ao + (size_t)m0 * 96);
        for (int idx = tid; idx < 128 * 48; idx += 256) {
            int r = idx / 48, c2 = idx - r * 48;
            float2 v = __half22float2(src[idx]);
            xs[r * 100 + c2 * 2]     = f2tf(v.x);
            xs[r * 100 + c2 * 2 + 1] = f2tf(v.y);
        }
    }
    __syncthreads();

    const int wp   = tid >> 5;
    const int lane = tid & 31;
    const int g    = lane >> 2;
    const int tig  = lane & 3;
    const int cg   = wp & 3;
    const int mh   = wp >> 2;

    uint2 breg[12][3];
    #pragma unroll
    for (int kk = 0; kk < 12; kk++)
        #pragma unroll
        for (int ntl = 0; ntl < 3; ntl++)
            breg[kk][ntl] = *(const uint2*)(wfrag + ((3 * cg + ntl) * 12 + kk) * 64 + lane * 2);

    #pragma unroll
    for (int s = 0; s < 4; s++) {
        const unsigned* xrA = xs + (mh * 64 + s * 16 + g) * 100;
        const unsigned* xrB = xrA + 800;

        float acc[3][4];
        #pragma unroll
        for (int ntl = 0; ntl < 3; ntl++)
            #pragma unroll
            for (int e = 0; e < 4; e++) acc[ntl][e] = 0.f;

        #pragma unroll
        for (int kk = 0; kk < 12; kk++) {
            unsigned a0 = xrA[kk * 8 + tig];
            unsigned a1 = xrB[kk * 8 + tig];
            unsigned a2 = xrA[kk * 8 + tig + 4];
            unsigned a3 = xrB[kk * 8 + tig + 4];
            #pragma unroll
            for (int ntl = 0; ntl < 3; ntl++)
                mma_tf32(acc[ntl][0], acc[ntl][1], acc[ntl][2], acc[ntl][3],
                         a0, a1, a2, a3, breg[kk][ntl].x, breg[kk][ntl].y);
        }

        const size_t mA = m0 + mh * 64 + s * 16 + g;
        const size_t mB = mA + 8;
        #pragma unroll
        for (int ntl = 0; ntl < 3; ntl++) {
            int c0 = (3 * cg + ntl) * 8 + 2 * tig;
            float bb0 = bs[c0], bb1 = bs[c0 + 1];
            *(float2*)(out + mA * 96 + c0) = make_float2(acc[ntl][0] + bb0, acc[ntl][1] + bb1);
            *(float2*)(out + mB * 96 + c0) = make_float2(acc[ntl][2] + bb0, acc[ntl][3] + bb1);
        }
    }
}

// ---------------- launch ---------------------------------------------------
extern "C" void kernel_launch(void* const* d_in, const int* in_sizes, int n_in,
                              void* d_out, int out_size) {
    const float* x      = (const float*)d_in[0];
    const float* mask   = (const float*)d_in[1];
    const float* qkv_w  = (const float*)d_in[2];
    const float* qkv_b  = (const float*)d_in[3];
    const float* proj_w = (const float*)d_in[4];
    const float* proj_b = (const float*)d_in[5];
    const float* rpb    = (const float*)d_in[6];
    const int*   relidx = (const int*)d_in[7];
    float* out = (float*)d_out;

    const int smem_attn = (5632 + 5632 + 9216 + 12800 + 288) * 4;  // 134,272 B
    const int smem_proj = (12800 + 9216 + 96) * 4;                 //  88,448 B
    cudaFuncSetAttribute(attn_kernel, cudaFuncAttributeMaxDynamicSharedMemorySize, smem_attn);
    cudaFuncSetAttribute(proj_kernel, cudaFuncAttributeMaxDynamicSharedMemorySize, smem_proj);

    cb_kernel  <<<dim3(NW * HEADS, 4), 352>>>(mask, rpb, relidx);
    attn_kernel<<<B_TOT * HEADS, 704, smem_attn>>>(x, qkv_w, qkv_b);
    proj_kernel<<<1372, 256, smem_proj>>>(proj_w, proj_b, out);
    (void)in_sizes; (void)n_in; (void)out_size;
}